// round 1
// baseline (speedup 1.0000x reference)
#include <cuda_runtime.h>

#define D_MODEL 1024
#define NHEAD   16
#define HEAD_DIM 64
#define BATCH   2
#define SEQ     2048
#define BT      (BATCH * SEQ)   // 4096 rows

// ---------------------------------------------------------------------------
// Scratch (device globals; no runtime allocation allowed)
// [0]=Q proj, [1]=K proj, [2]=V proj, [3]=attention output
// ---------------------------------------------------------------------------
__device__ float g_scratch[4][BT * D_MODEL];

// ---------------------------------------------------------------------------
// Packed fp32x2 helpers (Blackwell FFMA2 path — only reachable via PTX)
// ---------------------------------------------------------------------------
__device__ __forceinline__ unsigned long long pack2(float x, float y) {
    unsigned long long r;
    asm("mov.b64 %0, {%1, %2};" : "=l"(r) : "f"(x), "f"(y));
    return r;
}
__device__ __forceinline__ void ffma2(unsigned long long& d,
                                      unsigned long long a,
                                      unsigned long long b) {
    asm("fma.rn.f32x2 %0, %1, %2, %0;" : "+l"(d) : "l"(a), "l"(b));
}
__device__ __forceinline__ float2 unpack2(unsigned long long v) {
    float2 r;
    asm("mov.b64 {%0, %1}, %2;" : "=f"(r.x), "=f"(r.y) : "l"(v));
    return r;
}

// ---------------------------------------------------------------------------
// GEMM: C[M,N] = A[M,K] @ W[N,K]^T + bias   (torch Linear semantics)
// M=4096, N=1024, K=1024. BM=BN=128, BK=8, 256 threads, 8x8 per thread,
// inner product via packed f32x2 FMA.
// ---------------------------------------------------------------------------
#define GBM 128
#define GBN 128
#define GBK 8

__global__ void __launch_bounds__(256)
gemm_nt_bias(const float* __restrict__ A,
             const float* __restrict__ W,
             const float* __restrict__ bias,
             float* __restrict__ C) {
    const int K = D_MODEL;
    __shared__ float As[GBK][GBM];
    __shared__ float Bs[GBK][GBN];

    const int tid = threadIdx.x;
    const int bm = blockIdx.y * GBM;
    const int bn = blockIdx.x * GBN;
    const int tr = (tid >> 4) * 8;   // 0..120 row offset in tile
    const int tc = (tid & 15) * 8;   // 0..120 col offset in tile

    const int lRow = tid >> 1;         // 0..127
    const int lCol = (tid & 1) * 4;    // 0 or 4

    const float* Ap = A + (size_t)(bm + lRow) * K + lCol;
    const float* Wp = W + (size_t)(bn + lRow) * K + lCol;

    unsigned long long acc[8][4];
#pragma unroll
    for (int i = 0; i < 8; i++)
#pragma unroll
        for (int j = 0; j < 4; j++) acc[i][j] = 0ULL;

    for (int k0 = 0; k0 < K; k0 += GBK) {
        float4 av = *(const float4*)(Ap + k0);
        float4 wv = *(const float4*)(Wp + k0);
        As[lCol + 0][lRow] = av.x;
        As[lCol + 1][lRow] = av.y;
        As[lCol + 2][lRow] = av.z;
        As[lCol + 3][lRow] = av.w;
        Bs[lCol + 0][lRow] = wv.x;
        Bs[lCol + 1][lRow] = wv.y;
        Bs[lCol + 2][lRow] = wv.z;
        Bs[lCol + 3][lRow] = wv.w;
        __syncthreads();

#pragma unroll
        for (int kk = 0; kk < GBK; kk++) {
            float4 a0 = *(const float4*)&As[kk][tr];
            float4 a1 = *(const float4*)&As[kk][tr + 4];
            float4 b0 = *(const float4*)&Bs[kk][tc];
            float4 b1 = *(const float4*)&Bs[kk][tc + 4];
            unsigned long long rb[4];
            rb[0] = pack2(b0.x, b0.y);
            rb[1] = pack2(b0.z, b0.w);
            rb[2] = pack2(b1.x, b1.y);
            rb[3] = pack2(b1.z, b1.w);
            float ra[8] = {a0.x, a0.y, a0.z, a0.w, a1.x, a1.y, a1.z, a1.w};
#pragma unroll
            for (int i = 0; i < 8; i++) {
                unsigned long long ai = pack2(ra[i], ra[i]);
#pragma unroll
                for (int j = 0; j < 4; j++) ffma2(acc[i][j], ai, rb[j]);
            }
        }
        __syncthreads();
    }

    // epilogue: add bias, store
    float bb[8];
#pragma unroll
    for (int j = 0; j < 8; j++) bb[j] = bias[bn + tc + j];

#pragma unroll
    for (int i = 0; i < 8; i++) {
        const int gr = bm + tr + i;
        float* Cp = C + (size_t)gr * D_MODEL + bn + tc;
        float2 v0 = unpack2(acc[i][0]);
        float2 v1 = unpack2(acc[i][1]);
        float2 v2 = unpack2(acc[i][2]);
        float2 v3 = unpack2(acc[i][3]);
        float4 o0 = make_float4(v0.x + bb[0], v0.y + bb[1], v1.x + bb[2], v1.y + bb[3]);
        float4 o1 = make_float4(v2.x + bb[4], v2.y + bb[5], v3.x + bb[6], v3.y + bb[7]);
        *(float4*)Cp = o0;
        *(float4*)(Cp + 4) = o1;
    }
}

// ---------------------------------------------------------------------------
// Flash attention: one CTA per (batch, head, 64-row Q tile).
// 256 threads as 16x16 grid; each thread owns a 4x4 S microtile and a 4x4
// O microtile. Online softmax with per-row m/l carried in registers.
// Smem: natural [row][d] layout, stride 64 (no pad); conflict-free via
// per-lane d rotation in the S GEMM. K tile and P tile share one buffer.
// Total static smem = 3 * 64*64*4 = 48 KB exactly.
// ---------------------------------------------------------------------------
#define BQ  64
#define BKV 64

__global__ void __launch_bounds__(256)
attn_kernel(const float* __restrict__ Q,
            const float* __restrict__ Kg,
            const float* __restrict__ Vg,
            float* __restrict__ O) {
    __shared__ float Qs[BQ][HEAD_DIM];    // [q-row][d]
    __shared__ float KPs[BKV][HEAD_DIM];  // K tile [key][d], reused as P [q-row][key]
    __shared__ float Vs[BKV][HEAD_DIM];   // [key][d]

    const int tid = threadIdx.x;
    const int ty = tid >> 4;   // 0..15
    const int tx = tid & 15;   // 0..15
    const int ty4 = ty * 4;
    const int tx4 = tx * 4;

    const int qt = blockIdx.x;
    const int h  = blockIdx.y;
    const int b  = blockIdx.z;

    const float scale = 0.125f;  // 1/sqrt(64)
    const size_t hoff = (size_t)h * HEAD_DIM;
    const float* Qbase = Q + ((size_t)b * SEQ + (size_t)qt * BQ) * D_MODEL + hoff;
    const float* Kbase = Kg + (size_t)b * SEQ * D_MODEL + hoff;
    const float* Vbase = Vg + (size_t)b * SEQ * D_MODEL + hoff;

    // load Q tile (pre-scaled); 64 rows x 16 float4
#pragma unroll
    for (int t = tid; t < BQ * (HEAD_DIM / 4); t += 256) {
        int r = t >> 4;
        int c4 = (t & 15) << 2;
        float4 v = *(const float4*)(Qbase + (size_t)r * D_MODEL + c4);
        v.x *= scale; v.y *= scale; v.z *= scale; v.w *= scale;
        *(float4*)&Qs[r][c4] = v;
    }

    float m[4], l[4], o[4][4];
#pragma unroll
    for (int i = 0; i < 4; i++) {
        m[i] = -1e30f;
        l[i] = 0.0f;
#pragma unroll
        for (int j = 0; j < 4; j++) o[i][j] = 0.0f;
    }

    const int drot = (tx * 4) & 63;

    for (int kt = 0; kt < SEQ / BKV; kt++) {
        const float* Kt = Kbase + (size_t)kt * BKV * D_MODEL;
        const float* Vt = Vbase + (size_t)kt * BKV * D_MODEL;
#pragma unroll
        for (int t = tid; t < BKV * (HEAD_DIM / 4); t += 256) {
            int r = t >> 4;
            int c4 = (t & 15) << 2;
            *(float4*)&KPs[r][c4] = *(const float4*)(Kt + (size_t)r * D_MODEL + c4);
            *(float4*)&Vs[r][c4]  = *(const float4*)(Vt + (size_t)r * D_MODEL + c4);
        }
        __syncthreads();

        // S = Q K^T (4x4 per thread), d-rotated for conflict-free LDS
        float s[4][4];
#pragma unroll
        for (int i = 0; i < 4; i++)
#pragma unroll
            for (int j = 0; j < 4; j++) s[i][j] = 0.0f;

#pragma unroll
        for (int dd = 0; dd < HEAD_DIM; dd += 4) {
            const int d = (dd + drot) & 63;
            float4 qa[4], kb[4];
#pragma unroll
            for (int i = 0; i < 4; i++) qa[i] = *(const float4*)&Qs[ty4 + i][d];
#pragma unroll
            for (int j = 0; j < 4; j++) kb[j] = *(const float4*)&KPs[tx4 + j][d];
#pragma unroll
            for (int i = 0; i < 4; i++)
#pragma unroll
                for (int j = 0; j < 4; j++) {
                    s[i][j] += qa[i].x * kb[j].x;
                    s[i][j] += qa[i].y * kb[j].y;
                    s[i][j] += qa[i].z * kb[j].z;
                    s[i][j] += qa[i].w * kb[j].w;
                }
        }
        __syncthreads();  // done reading K tile; KPs becomes P

        // online softmax per row (16 lanes per row group; xor-shuffle reduce)
#pragma unroll
        for (int i = 0; i < 4; i++) {
            float rm = fmaxf(fmaxf(s[i][0], s[i][1]), fmaxf(s[i][2], s[i][3]));
#pragma unroll
            for (int off = 8; off >= 1; off >>= 1)
                rm = fmaxf(rm, __shfl_xor_sync(0xffffffffu, rm, off));
            float mn = fmaxf(m[i], rm);
            float corr = __expf(m[i] - mn);
            m[i] = mn;
            float p0 = __expf(s[i][0] - mn);
            float p1 = __expf(s[i][1] - mn);
            float p2 = __expf(s[i][2] - mn);
            float p3 = __expf(s[i][3] - mn);
            float rs = p0 + p1 + p2 + p3;
#pragma unroll
            for (int off = 8; off >= 1; off >>= 1)
                rs += __shfl_xor_sync(0xffffffffu, rs, off);
            l[i] = l[i] * corr + rs;
#pragma unroll
            for (int j = 0; j < 4; j++) o[i][j] *= corr;
            *(float4*)&KPs[ty4 + i][tx4] = make_float4(p0, p1, p2, p3);
        }
        __syncthreads();  // P visible to all

        // O += P V  (P: [q-row][key] in KPs, V: [key][d])
#pragma unroll
        for (int k4 = 0; k4 < BKV; k4 += 4) {
            float4 pv[4], vv[4];
#pragma unroll
            for (int i = 0; i < 4; i++) pv[i] = *(const float4*)&KPs[ty4 + i][k4];
#pragma unroll
            for (int kk = 0; kk < 4; kk++) vv[kk] = *(const float4*)&Vs[k4 + kk][tx4];
#pragma unroll
            for (int i = 0; i < 4; i++) {
                o[i][0] += pv[i].x * vv[0].x + pv[i].y * vv[1].x + pv[i].z * vv[2].x + pv[i].w * vv[3].x;
                o[i][1] += pv[i].x * vv[0].y + pv[i].y * vv[1].y + pv[i].z * vv[2].y + pv[i].w * vv[3].y;
                o[i][2] += pv[i].x * vv[0].z + pv[i].y * vv[1].z + pv[i].z * vv[2].z + pv[i].w * vv[3].z;
                o[i][3] += pv[i].x * vv[0].w + pv[i].y * vv[1].w + pv[i].z * vv[2].w + pv[i].w * vv[3].w;
            }
        }
        __syncthreads();  // done reading P/V before next tile load
    }

    // normalize and write (layout [b,t,D] with head offset)
#pragma unroll
    for (int i = 0; i < 4; i++) {
        float inv = 1.0f / l[i];
        size_t row = (size_t)b * SEQ + (size_t)qt * BQ + ty4 + i;
        float4 out = make_float4(o[i][0] * inv, o[i][1] * inv, o[i][2] * inv, o[i][3] * inv);
        *(float4*)(O + row * D_MODEL + hoff + tx4) = out;
    }
}

// ---------------------------------------------------------------------------
// launch
// ---------------------------------------------------------------------------
extern "C" void kernel_launch(void* const* d_in, const int* in_sizes, int n_in,
                              void* d_out, int out_size) {
    (void)in_sizes; (void)n_in; (void)out_size;

    const float* q  = (const float*)d_in[0];
    const float* k  = (const float*)d_in[1];
    const float* v  = (const float*)d_in[2];
    const float* Wq = (const float*)d_in[3];
    const float* bq = (const float*)d_in[4];
    const float* Wk = (const float*)d_in[5];
    const float* bk = (const float*)d_in[6];
    const float* Wv = (const float*)d_in[7];
    const float* bv = (const float*)d_in[8];
    const float* Wo = (const float*)d_in[9];
    const float* bo = (const float*)d_in[10];
    float* out = (float*)d_out;

    void* sym = nullptr;
    cudaGetSymbolAddress(&sym, g_scratch);
    float* sq = (float*)sym;
    float* sk = sq + (size_t)BT * D_MODEL;
    float* sv = sk + (size_t)BT * D_MODEL;
    float* so = sv + (size_t)BT * D_MODEL;

    dim3 gGrid(D_MODEL / GBN, BT / GBM);  // (8, 32)
    gemm_nt_bias<<<gGrid, 256>>>(q, Wq, bq, sq);
    gemm_nt_bias<<<gGrid, 256>>>(k, Wk, bk, sk);
    gemm_nt_bias<<<gGrid, 256>>>(v, Wv, bv, sv);

    dim3 aGrid(SEQ / BQ, NHEAD, BATCH);   // (32, 16, 2)
    attn_kernel<<<aGrid, 256>>>(sq, sk, sv, so);

    gemm_nt_bias<<<gGrid, 256>>>(so, Wo, bo, out);
}

// round 5
// speedup vs baseline: 2.7030x; 2.7030x over previous
#include <cuda_runtime.h>
#include <cstdint>

#define D_MODEL 1024
#define NHEAD   16
#define HEAD_DIM 64
#define BATCH   2
#define SEQ     2048
#define BT      (BATCH * SEQ)   // 4096 rows

// ---------------------------------------------------------------------------
// Scratch (device globals; no runtime allocation allowed)
// ---------------------------------------------------------------------------
__device__ float g_scratch[4][BT * D_MODEL];           // sq, sk, sv, so
__device__ float g_rin[3][BT * D_MODEL];               // tf32-rounded q,k,v
__device__ float g_rw[4][D_MODEL * D_MODEL];           // tf32-rounded weights

// ---------------------------------------------------------------------------
// Helpers
// ---------------------------------------------------------------------------
__device__ __forceinline__ uint32_t smem_u32(const void* p) {
    uint32_t a;
    asm("{ .reg .u64 t; cvta.to.shared.u64 t, %1; cvt.u32.u64 %0, t; }" : "=r"(a) : "l"(p));
    return a;
}
__device__ __forceinline__ float round_tf32(float x) {
    uint32_t r;
    asm("cvt.rna.tf32.f32 %0, %1;" : "=r"(r) : "f"(x));
    return __uint_as_float(r);
}
__device__ __forceinline__ void cpasync16(uint32_t dst, const void* src) {
    asm volatile("cp.async.cg.shared.global [%0], [%1], 16;" :: "r"(dst), "l"(src) : "memory");
}
__device__ __forceinline__ void cp_commit() {
    asm volatile("cp.async.commit_group;" ::: "memory");
}
template <int N>
__device__ __forceinline__ void cp_wait_group() {
    asm volatile("cp.async.wait_group %0;" :: "n"(N) : "memory");
}

// mma.sync m16n8k8 tf32. Fragment layout (CUTLASS SM80_16x8x8_F32TF32TF32F32_TN):
//   A: a0=(g,lr) a1=(g+8,lr) a2=(g,lr+4) a3=(g+8,lr+4)      [g=lane>>2, lr=lane&3]
//   B: b0=B[lr][g] b1=B[lr+4][g]          (B is KxN)
//   C: c0=(g,2lr) c1=(g,2lr+1) c2=(g+8,2lr) c3=(g+8,2lr+1)
__device__ __forceinline__ void mma_tf32(float& d0, float& d1, float& d2, float& d3,
                                         uint32_t a0, uint32_t a1, uint32_t a2, uint32_t a3,
                                         uint32_t b0, uint32_t b1) {
    asm volatile(
        "mma.sync.aligned.m16n8k8.row.col.f32.tf32.tf32.f32 "
        "{%0,%1,%2,%3}, {%4,%5,%6,%7}, {%8,%9}, {%0,%1,%2,%3};"
        : "+f"(d0), "+f"(d1), "+f"(d2), "+f"(d3)
        : "r"(a0), "r"(a1), "r"(a2), "r"(a3), "r"(b0), "r"(b1));
}

// ---------------------------------------------------------------------------
// tf32 rounding pre-pass
// ---------------------------------------------------------------------------
__global__ void round_tf32_kernel(const float* __restrict__ in, float* __restrict__ out, int n4) {
    int i = blockIdx.x * blockDim.x + threadIdx.x;
    int stride = gridDim.x * blockDim.x;
    for (; i < n4; i += stride) {
        float4 v = ((const float4*)in)[i];
        v.x = round_tf32(v.x);
        v.y = round_tf32(v.y);
        v.z = round_tf32(v.z);
        v.w = round_tf32(v.w);
        ((float4*)out)[i] = v;
    }
}

// ---------------------------------------------------------------------------
// GEMM: C[M,1024] = A[M,1024] @ W[1024,1024]^T + bias  via mma.sync tf32.
// CTA 128x128, 8 warps in 2x4 (warp tile 64x32), K-step 16, 4-stage cp.async.
// GPAD=20 -> fragment LDS banks 20*lq+lr mod 32 all distinct (conflict-free).
// ---------------------------------------------------------------------------
#define GSTG 4
#define GPAD 20
#define G_STAGE_FLOATS (2 * 128 * GPAD)        // 5120 floats per stage
#define GEMM_SMEM (GSTG * G_STAGE_FLOATS * 4)  // 81920 bytes
#define G_NS (D_MODEL / 16)                    // 64 K-steps

__global__ void __launch_bounds__(256, 2)
gemm_mma_tf32(const float* __restrict__ A,
              const float* __restrict__ W,
              const float* __restrict__ bias,
              float* __restrict__ C,
              int round_out) {
    extern __shared__ float smf[];
    const uint32_t sb = smem_u32(smf);
    const int tid = threadIdx.x;
    const int wid = tid >> 5;
    const int lane = tid & 31;
    const int lq = lane >> 2;     // 0..7
    const int lr = lane & 3;      // 0..3

    const int bm = blockIdx.y * 128;
    const int bn = blockIdx.x * 128;
    const int warpRow = (wid & 1) * 64;
    const int warpCol = (wid >> 1) * 32;

    const int l_row0 = tid >> 2;          // rows 0..63
    const int l_ch0  = tid & 3;
    const int l_row1 = l_row0 + 64;       // rows 64..127

    auto load_stage = [&](int s) {
        const int k0 = s * 16;
        const uint32_t smA = sb + (uint32_t)(s & (GSTG - 1)) * (G_STAGE_FLOATS * 4);
        const uint32_t smB = smA + 128 * GPAD * 4;
        cpasync16(smA + l_row0 * (GPAD * 4) + l_ch0 * 16,
                  A + (size_t)(bm + l_row0) * D_MODEL + k0 + l_ch0 * 4);
        cpasync16(smA + l_row1 * (GPAD * 4) + l_ch0 * 16,
                  A + (size_t)(bm + l_row1) * D_MODEL + k0 + l_ch0 * 4);
        cpasync16(smB + l_row0 * (GPAD * 4) + l_ch0 * 16,
                  W + (size_t)(bn + l_row0) * D_MODEL + k0 + l_ch0 * 4);
        cpasync16(smB + l_row1 * (GPAD * 4) + l_ch0 * 16,
                  W + (size_t)(bn + l_row1) * D_MODEL + k0 + l_ch0 * 4);
        cp_commit();
    };

    float acc[4][4][4];
#pragma unroll
    for (int i = 0; i < 4; i++)
#pragma unroll
        for (int j = 0; j < 4; j++)
#pragma unroll
            for (int r = 0; r < 4; r++) acc[i][j][r] = 0.0f;

    load_stage(0);
    load_stage(1);
    load_stage(2);

    for (int s = 0; s < G_NS; s++) {
        cp_wait_group<2>();
        __syncthreads();
        if (s + 3 < G_NS) load_stage(s + 3); else cp_commit();

        const float* As = smf + (size_t)(s & (GSTG - 1)) * G_STAGE_FLOATS;
        const float* Ws = As + 128 * GPAD;

#pragma unroll
        for (int kc = 0; kc < 2; kc++) {
            const int kk = kc * 8 + lr;
            uint32_t af[4][4];
#pragma unroll
            for (int mf = 0; mf < 4; mf++) {
                const int r = warpRow + mf * 16 + lq;
                af[mf][0] = __float_as_uint(As[r * GPAD + kk]);
                af[mf][1] = __float_as_uint(As[(r + 8) * GPAD + kk]);
                af[mf][2] = __float_as_uint(As[r * GPAD + kk + 4]);
                af[mf][3] = __float_as_uint(As[(r + 8) * GPAD + kk + 4]);
            }
            uint32_t bf[4][2];
#pragma unroll
            for (int nf = 0; nf < 4; nf++) {
                const int n = warpCol + nf * 8 + lq;
                bf[nf][0] = __float_as_uint(Ws[n * GPAD + kk]);
                bf[nf][1] = __float_as_uint(Ws[n * GPAD + kk + 4]);
            }
#pragma unroll
            for (int mf = 0; mf < 4; mf++)
#pragma unroll
                for (int nf = 0; nf < 4; nf++)
                    mma_tf32(acc[mf][nf][0], acc[mf][nf][1], acc[mf][nf][2], acc[mf][nf][3],
                             af[mf][0], af[mf][1], af[mf][2], af[mf][3],
                             bf[nf][0], bf[nf][1]);
        }
        __syncthreads();
    }

    // epilogue: cols 2lr,2lr+1 at rows lq / lq+8
#pragma unroll
    for (int nf = 0; nf < 4; nf++) {
        const int col = bn + warpCol + nf * 8 + 2 * lr;
        const float b0 = bias[col];
        const float b1 = bias[col + 1];
#pragma unroll
        for (int mf = 0; mf < 4; mf++) {
            const int row = bm + warpRow + mf * 16 + lq;
            float v0 = acc[mf][nf][0] + b0;
            float v1 = acc[mf][nf][1] + b1;
            float v2 = acc[mf][nf][2] + b0;
            float v3 = acc[mf][nf][3] + b1;
            if (round_out) {
                v0 = round_tf32(v0); v1 = round_tf32(v1);
                v2 = round_tf32(v2); v3 = round_tf32(v3);
            }
            *(float2*)(C + (size_t)row * D_MODEL + col) = make_float2(v0, v1);
            *(float2*)(C + (size_t)(row + 8) * D_MODEL + col) = make_float2(v2, v3);
        }
    }
}

// ---------------------------------------------------------------------------
// Flash attention on mma.sync tf32.
// CTA = (b, h, 128 Q rows). 8 warps x 16 rows. BKV=64, 2-stage cp.async.
// P permuted D-frag -> A-frag via quad shuffles (exact, stays in registers).
// ---------------------------------------------------------------------------
#define AQ_ROWS 128
#define AKV     64
#define APAD    68
#define A_QS_F   (AQ_ROWS * APAD)               // 8704 floats
#define A_KST_F  (AKV * APAD)                   // 4352 floats
#define ATT_SMEM ((A_QS_F + 4 * A_KST_F) * 4)   // 104448 bytes
#define NKT (SEQ / AKV)                         // 32 kv tiles

__global__ void __launch_bounds__(256, 1)
attn_mma(const float* __restrict__ Q,
         const float* __restrict__ Kg,
         const float* __restrict__ Vg,
         float* __restrict__ O) {
    extern __shared__ float smf[];
    float* Qs = smf;                        // [128][68]
    float* Ks[2] = { smf + A_QS_F, smf + A_QS_F + A_KST_F };
    float* Vs[2] = { smf + A_QS_F + 2 * A_KST_F, smf + A_QS_F + 3 * A_KST_F };
    const uint32_t sb = smem_u32(smf);

    const int tid = threadIdx.x;
    const int wid = tid >> 5;
    const int lane = tid & 31;
    const int lq = lane >> 2;
    const int lr = lane & 3;
    const int wrow = wid * 16;

    const int qt = blockIdx.x;
    const int h  = blockIdx.y;
    const int b  = blockIdx.z;

    const float* Qbase = Q + ((size_t)b * SEQ + (size_t)qt * AQ_ROWS) * D_MODEL + h * HEAD_DIM;
    const float* Kbase = Kg + (size_t)b * SEQ * D_MODEL + h * HEAD_DIM;
    const float* Vbase = Vg + (size_t)b * SEQ * D_MODEL + h * HEAD_DIM;

    auto load_kv = [&](int kt) {
        const int st = kt & 1;
        const uint32_t kdst = sb + (uint32_t)(A_QS_F + st * A_KST_F) * 4;
        const uint32_t vdst = sb + (uint32_t)(A_QS_F + (2 + st) * A_KST_F) * 4;
        const float* Kt = Kbase + (size_t)kt * AKV * D_MODEL;
        const float* Vt = Vbase + (size_t)kt * AKV * D_MODEL;
#pragma unroll
        for (int i = 0; i < 4; i++) {
            const int id = tid + i * 256;
            const int row = id >> 4;
            const int ch = id & 15;
            cpasync16(kdst + row * (APAD * 4) + ch * 16, Kt + (size_t)row * D_MODEL + ch * 4);
            cpasync16(vdst + row * (APAD * 4) + ch * 16, Vt + (size_t)row * D_MODEL + ch * 4);
        }
        cp_commit();
    };

    load_kv(0);

    // Q tile -> smem, scaled by 1/8. 128 rows x 16 chunks = 2048 float4 tasks.
#pragma unroll
    for (int i = 0; i < 8; i++) {
        const int t = tid + i * 256;
        const int row = t >> 4;
        const int c4 = (t & 15) * 4;
        float4 v = *(const float4*)(Qbase + (size_t)row * D_MODEL + c4);
        v.x *= 0.125f; v.y *= 0.125f; v.z *= 0.125f; v.w *= 0.125f;
        *(float4*)&Qs[row * APAD + c4] = v;
    }
    __syncthreads();

    // Q A-fragments: 8 k-chunks x 4 regs
    uint32_t qa[8][4];
#pragma unroll
    for (int kc = 0; kc < 8; kc++) {
        const int r = wrow + lq;
        const int d = kc * 8 + lr;
        qa[kc][0] = __float_as_uint(Qs[r * APAD + d]);
        qa[kc][1] = __float_as_uint(Qs[(r + 8) * APAD + d]);
        qa[kc][2] = __float_as_uint(Qs[r * APAD + d + 4]);
        qa[kc][3] = __float_as_uint(Qs[(r + 8) * APAD + d + 4]);
    }

    float m0 = -1e30f, m1 = -1e30f, l0 = 0.0f, l1 = 0.0f;
    float o[8][4];
#pragma unroll
    for (int nf = 0; nf < 8; nf++)
#pragma unroll
        for (int r = 0; r < 4; r++) o[nf][r] = 0.0f;

    for (int kt = 0; kt < NKT; kt++) {
        cp_wait_group<0>();
        __syncthreads();
        if (kt + 1 < NKT) load_kv(kt + 1);

        const int st = kt & 1;
        const float* Kst = Ks[st];
        const float* Vst = Vs[st];

        // S = Q K^T
        float s[8][4];
#pragma unroll
        for (int nf = 0; nf < 8; nf++) {
            s[nf][0] = s[nf][1] = s[nf][2] = s[nf][3] = 0.0f;
            const int key = nf * 8 + lq;
#pragma unroll
            for (int kc = 0; kc < 8; kc++) {
                const int d = kc * 8 + lr;
                uint32_t b0 = __float_as_uint(Kst[key * APAD + d]);
                uint32_t b1 = __float_as_uint(Kst[key * APAD + d + 4]);
                mma_tf32(s[nf][0], s[nf][1], s[nf][2], s[nf][3],
                         qa[kc][0], qa[kc][1], qa[kc][2], qa[kc][3], b0, b1);
            }
        }

        // online softmax: regs 0,1 -> row wrow+lq; regs 2,3 -> row wrow+lq+8
        float mx0 = -1e30f, mx1 = -1e30f;
#pragma unroll
        for (int nf = 0; nf < 8; nf++) {
            mx0 = fmaxf(mx0, fmaxf(s[nf][0], s[nf][1]));
            mx1 = fmaxf(mx1, fmaxf(s[nf][2], s[nf][3]));
        }
        mx0 = fmaxf(mx0, __shfl_xor_sync(0xffffffffu, mx0, 1));
        mx0 = fmaxf(mx0, __shfl_xor_sync(0xffffffffu, mx0, 2));
        mx1 = fmaxf(mx1, __shfl_xor_sync(0xffffffffu, mx1, 1));
        mx1 = fmaxf(mx1, __shfl_xor_sync(0xffffffffu, mx1, 2));

        const float mn0 = fmaxf(m0, mx0);
        const float mn1 = fmaxf(m1, mx1);
        const float c0 = __expf(m0 - mn0);
        const float c1 = __expf(m1 - mn1);
        m0 = mn0; m1 = mn1;

        float rs0 = 0.0f, rs1 = 0.0f;
#pragma unroll
        for (int nf = 0; nf < 8; nf++) {
            s[nf][0] = round_tf32(__expf(s[nf][0] - mn0));
            s[nf][1] = round_tf32(__expf(s[nf][1] - mn0));
            s[nf][2] = round_tf32(__expf(s[nf][2] - mn1));
            s[nf][3] = round_tf32(__expf(s[nf][3] - mn1));
            rs0 += s[nf][0] + s[nf][1];
            rs1 += s[nf][2] + s[nf][3];
        }
        rs0 += __shfl_xor_sync(0xffffffffu, rs0, 1);
        rs0 += __shfl_xor_sync(0xffffffffu, rs0, 2);
        rs1 += __shfl_xor_sync(0xffffffffu, rs1, 1);
        rs1 += __shfl_xor_sync(0xffffffffu, rs1, 2);
        l0 = l0 * c0 + rs0;
        l1 = l1 * c1 + rs1;

#pragma unroll
        for (int nf = 0; nf < 8; nf++) {
            o[nf][0] *= c0; o[nf][1] *= c0;
            o[nf][2] *= c1; o[nf][3] *= c1;
        }

        // permute P: D-frag cols {2t,2t+1} -> A-frag cols {t, t+4}
        uint32_t pa[8][4];
        const int qb = lane & ~3;
        const int sA = qb | (lr >> 1);
        const int sB = qb | ((lr >> 1) + 2);
        const bool odd = (lr & 1);
#pragma unroll
        for (int kc = 0; kc < 8; kc++) {
            float x0 = __shfl_sync(0xffffffffu, s[kc][0], sA);
            float x1 = __shfl_sync(0xffffffffu, s[kc][1], sA);
            float y0 = __shfl_sync(0xffffffffu, s[kc][0], sB);
            float y1 = __shfl_sync(0xffffffffu, s[kc][1], sB);
            pa[kc][0] = __float_as_uint(odd ? x1 : x0);
            pa[kc][2] = __float_as_uint(odd ? y1 : y0);
            float z0 = __shfl_sync(0xffffffffu, s[kc][2], sA);
            float z1 = __shfl_sync(0xffffffffu, s[kc][3], sA);
            float w0 = __shfl_sync(0xffffffffu, s[kc][2], sB);
            float w1 = __shfl_sync(0xffffffffu, s[kc][3], sB);
            pa[kc][1] = __float_as_uint(odd ? z1 : z0);
            pa[kc][3] = __float_as_uint(odd ? w1 : w0);
        }

        // O += P V
#pragma unroll
        for (int nf2 = 0; nf2 < 8; nf2++) {
            const int dh = nf2 * 8 + lq;
#pragma unroll
            for (int kc = 0; kc < 8; kc++) {
                const int key = kc * 8 + lr;
                uint32_t b0 = __float_as_uint(Vst[key * APAD + dh]);
                uint32_t b1 = __float_as_uint(Vst[(key + 4) * APAD + dh]);
                mma_tf32(o[nf2][0], o[nf2][1], o[nf2][2], o[nf2][3],
                         pa[kc][0], pa[kc][1], pa[kc][2], pa[kc][3], b0, b1);
            }
        }
        __syncthreads();
    }

    // epilogue: normalize, round (feeds Wo mma GEMM), store
    const float inv0 = 1.0f / l0;
    const float inv1 = 1.0f / l1;
    const size_t row0 = (size_t)b * SEQ + (size_t)qt * AQ_ROWS + wrow + lq;
#pragma unroll
    for (int nf2 = 0; nf2 < 8; nf2++) {
        const int col = h * HEAD_DIM + nf2 * 8 + 2 * lr;
        *(float2*)(O + row0 * D_MODEL + col) =
            make_float2(round_tf32(o[nf2][0] * inv0), round_tf32(o[nf2][1] * inv0));
        *(float2*)(O + (row0 + 8) * D_MODEL + col) =
            make_float2(round_tf32(o[nf2][2] * inv1), round_tf32(o[nf2][3] * inv1));
    }
}

// ---------------------------------------------------------------------------
// launch
// ---------------------------------------------------------------------------
extern "C" void kernel_launch(void* const* d_in, const int* in_sizes, int n_in,
                              void* d_out, int out_size) {
    (void)in_sizes; (void)n_in; (void)out_size;

    const float* q  = (const float*)d_in[0];
    const float* k  = (const float*)d_in[1];
    const float* v  = (const float*)d_in[2];
    const float* Wq = (const float*)d_in[3];
    const float* bq = (const float*)d_in[4];
    const float* Wk = (const float*)d_in[5];
    const float* bk = (const float*)d_in[6];
    const float* Wv = (const float*)d_in[7];
    const float* bv = (const float*)d_in[8];
    const float* Wo = (const float*)d_in[9];
    const float* bo = (const float*)d_in[10];
    float* out = (float*)d_out;

    void* sym = nullptr;
    cudaGetSymbolAddress(&sym, g_scratch);
    float* sq = (float*)sym;
    float* sk = sq + (size_t)BT * D_MODEL;
    float* sv = sk + (size_t)BT * D_MODEL;
    float* so = sv + (size_t)BT * D_MODEL;

    void* symr = nullptr;
    cudaGetSymbolAddress(&symr, g_rin);
    float* rq = (float*)symr;
    float* rk = rq + (size_t)BT * D_MODEL;
    float* rv = rk + (size_t)BT * D_MODEL;

    void* symw = nullptr;
    cudaGetSymbolAddress(&symw, g_rw);
    float* rwq = (float*)symw;
    float* rwk = rwq + (size_t)D_MODEL * D_MODEL;
    float* rwv = rwk + (size_t)D_MODEL * D_MODEL;
    float* rwo = rwv + (size_t)D_MODEL * D_MODEL;

    static bool attr_done = false;
    if (!attr_done) {
        cudaFuncSetAttribute(gemm_mma_tf32, cudaFuncAttributeMaxDynamicSharedMemorySize, GEMM_SMEM);
        cudaFuncSetAttribute(attn_mma, cudaFuncAttributeMaxDynamicSharedMemorySize, ATT_SMEM);
        attr_done = true;
    }

    const int n4_in = BT * D_MODEL / 4;
    const int n4_w  = D_MODEL * D_MODEL / 4;
    round_tf32_kernel<<<1024, 256>>>(q, rq, n4_in);
    round_tf32_kernel<<<1024, 256>>>(k, rk, n4_in);
    round_tf32_kernel<<<1024, 256>>>(v, rv, n4_in);
    round_tf32_kernel<<<512, 256>>>(Wq, rwq, n4_w);
    round_tf32_kernel<<<512, 256>>>(Wk, rwk, n4_w);
    round_tf32_kernel<<<512, 256>>>(Wv, rwv, n4_w);
    round_tf32_kernel<<<512, 256>>>(Wo, rwo, n4_w);

    dim3 gGrid(D_MODEL / 128, BT / 128);  // (8, 32)
    gemm_mma_tf32<<<gGrid, 256, GEMM_SMEM>>>(rq, rwq, bq, sq, 1);
    gemm_mma_tf32<<<gGrid, 256, GEMM_SMEM>>>(rk, rwk, bk, sk, 1);
    gemm_mma_tf32<<<gGrid, 256, GEMM_SMEM>>>(rv, rwv, bv, sv, 1);

    dim3 aGrid(SEQ / AQ_ROWS, NHEAD, BATCH);  // (16, 16, 2)
    attn_mma<<<aGrid, 256, ATT_SMEM>>>(sq, sk, sv, so);

    gemm_mma_tf32<<<gGrid, 256, GEMM_SMEM>>>(so, rwo, bo, out, 0);
}

// round 6
// speedup vs baseline: 2.8829x; 1.0666x over previous
#include <cuda_runtime.h>
#include <cstdint>

#define D_MODEL 1024
#define NHEAD   16
#define HEAD_DIM 64
#define BATCH   2
#define SEQ     2048
#define BT      (BATCH * SEQ)   // 4096 rows

// ---------------------------------------------------------------------------
// Scratch (device globals; no runtime allocation allowed)
// ---------------------------------------------------------------------------
__device__ float g_scratch[4][BT * D_MODEL];           // sq, sk, sv, so
__device__ float g_rin[3][BT * D_MODEL];               // tf32-rounded q,k,v
__device__ float g_rw[4][D_MODEL * D_MODEL];           // tf32-rounded weights

// ---------------------------------------------------------------------------
// Helpers
// ---------------------------------------------------------------------------
__device__ __forceinline__ uint32_t smem_u32(const void* p) {
    uint32_t a;
    asm("{ .reg .u64 t; cvta.to.shared.u64 t, %1; cvt.u32.u64 %0, t; }" : "=r"(a) : "l"(p));
    return a;
}
__device__ __forceinline__ float round_tf32(float x) {
    uint32_t r;
    asm("cvt.rna.tf32.f32 %0, %1;" : "=r"(r) : "f"(x));
    return __uint_as_float(r);
}
__device__ __forceinline__ void cpasync16(uint32_t dst, const void* src) {
    asm volatile("cp.async.cg.shared.global [%0], [%1], 16;" :: "r"(dst), "l"(src) : "memory");
}
__device__ __forceinline__ void cp_commit() {
    asm volatile("cp.async.commit_group;" ::: "memory");
}
template <int N>
__device__ __forceinline__ void cp_wait_group() {
    asm volatile("cp.async.wait_group %0;" :: "n"(N) : "memory");
}

// mma.sync m16n8k8 tf32. Fragment layout (CUTLASS SM80_16x8x8_F32TF32TF32F32_TN):
//   A: a0=(g,lr) a1=(g+8,lr) a2=(g,lr+4) a3=(g+8,lr+4)      [g=lane>>2, lr=lane&3]
//   B: b0=B[lr][g] b1=B[lr+4][g]          (B is KxN)
//   C: c0=(g,2lr) c1=(g,2lr+1) c2=(g+8,2lr) c3=(g+8,2lr+1)
__device__ __forceinline__ void mma_tf32(float& d0, float& d1, float& d2, float& d3,
                                         uint32_t a0, uint32_t a1, uint32_t a2, uint32_t a3,
                                         uint32_t b0, uint32_t b1) {
    asm volatile(
        "mma.sync.aligned.m16n8k8.row.col.f32.tf32.tf32.f32 "
        "{%0,%1,%2,%3}, {%4,%5,%6,%7}, {%8,%9}, {%0,%1,%2,%3};"
        : "+f"(d0), "+f"(d1), "+f"(d2), "+f"(d3)
        : "r"(a0), "r"(a1), "r"(a2), "r"(a3), "r"(b0), "r"(b1));
}

// ---------------------------------------------------------------------------
// tf32 rounding pre-passes
// ---------------------------------------------------------------------------
__global__ void round_tf32_kernel(const float* __restrict__ in, float* __restrict__ out, int n4) {
    int i = blockIdx.x * blockDim.x + threadIdx.x;
    int stride = gridDim.x * blockDim.x;
    for (; i < n4; i += stride) {
        float4 v = ((const float4*)in)[i];
        v.x = round_tf32(v.x);
        v.y = round_tf32(v.y);
        v.z = round_tf32(v.z);
        v.w = round_tf32(v.w);
        ((float4*)out)[i] = v;
    }
}

struct Ptr4 { const float* in[4]; float* out[4]; };

__global__ void round_tf32_multi(Ptr4 p, int n4) {
    const float* in = p.in[blockIdx.y];
    float* out = p.out[blockIdx.y];
    int i = blockIdx.x * blockDim.x + threadIdx.x;
    int stride = gridDim.x * blockDim.x;
    for (; i < n4; i += stride) {
        float4 v = ((const float4*)in)[i];
        v.x = round_tf32(v.x);
        v.y = round_tf32(v.y);
        v.z = round_tf32(v.z);
        v.w = round_tf32(v.w);
        ((float4*)out)[i] = v;
    }
}

// ---------------------------------------------------------------------------
// GEMM: C[M,1024] = A[M,1024] @ W[1024,1024]^T + bias  via mma.sync tf32.
// CTA 128x128, 8 warps in 2x4 (warp tile 64x32), K-step 16, 4-stage cp.async.
// GPAD=20 -> fragment LDS banks (20*lq+lr) mod 32 all distinct.
// blockIdx.z selects the (A, W, bias, C) tuple -> q/k/v fused in one launch.
// ---------------------------------------------------------------------------
#define GSTG 4
#define GPAD 20
#define G_STAGE_FLOATS (2 * 128 * GPAD)        // 5120 floats per stage
#define GEMM_SMEM (GSTG * G_STAGE_FLOATS * 4)  // 81920 bytes
#define G_NS (D_MODEL / 16)                    // 64 K-steps

struct GemmArgs {
    const float* A[3];
    const float* W[3];
    const float* b[3];
    float* C[3];
    int round_out;
};

__global__ void __launch_bounds__(256, 2)
gemm_mma_tf32(GemmArgs ga) {
    extern __shared__ float smf[];
    const uint32_t sb = smem_u32(smf);
    const int tid = threadIdx.x;
    const int wid = tid >> 5;
    const int lane = tid & 31;
    const int lq = lane >> 2;
    const int lr = lane & 3;

    const float* __restrict__ A = ga.A[blockIdx.z];
    const float* __restrict__ W = ga.W[blockIdx.z];
    const float* __restrict__ bias = ga.b[blockIdx.z];
    float* __restrict__ C = ga.C[blockIdx.z];
    const int round_out = ga.round_out;

    const int bm = blockIdx.y * 128;
    const int bn = blockIdx.x * 128;
    const int warpRow = (wid & 1) * 64;
    const int warpCol = (wid >> 1) * 32;

    const int l_row0 = tid >> 2;
    const int l_ch0  = tid & 3;
    const int l_row1 = l_row0 + 64;

    auto load_stage = [&](int s) {
        const int k0 = s * 16;
        const uint32_t smA = sb + (uint32_t)(s & (GSTG - 1)) * (G_STAGE_FLOATS * 4);
        const uint32_t smB = smA + 128 * GPAD * 4;
        cpasync16(smA + l_row0 * (GPAD * 4) + l_ch0 * 16,
                  A + (size_t)(bm + l_row0) * D_MODEL + k0 + l_ch0 * 4);
        cpasync16(smA + l_row1 * (GPAD * 4) + l_ch0 * 16,
                  A + (size_t)(bm + l_row1) * D_MODEL + k0 + l_ch0 * 4);
        cpasync16(smB + l_row0 * (GPAD * 4) + l_ch0 * 16,
                  W + (size_t)(bn + l_row0) * D_MODEL + k0 + l_ch0 * 4);
        cpasync16(smB + l_row1 * (GPAD * 4) + l_ch0 * 16,
                  W + (size_t)(bn + l_row1) * D_MODEL + k0 + l_ch0 * 4);
        cp_commit();
    };

    float acc[4][4][4];
#pragma unroll
    for (int i = 0; i < 4; i++)
#pragma unroll
        for (int j = 0; j < 4; j++)
#pragma unroll
            for (int r = 0; r < 4; r++) acc[i][j][r] = 0.0f;

    load_stage(0);
    load_stage(1);
    load_stage(2);

    for (int s = 0; s < G_NS; s++) {
        cp_wait_group<2>();
        __syncthreads();
        if (s + 3 < G_NS) load_stage(s + 3); else cp_commit();

        const float* As = smf + (size_t)(s & (GSTG - 1)) * G_STAGE_FLOATS;
        const float* Ws = As + 128 * GPAD;

#pragma unroll
        for (int kc = 0; kc < 2; kc++) {
            const int kk = kc * 8 + lr;
            uint32_t af[4][4];
#pragma unroll
            for (int mf = 0; mf < 4; mf++) {
                const int r = warpRow + mf * 16 + lq;
                af[mf][0] = __float_as_uint(As[r * GPAD + kk]);
                af[mf][1] = __float_as_uint(As[(r + 8) * GPAD + kk]);
                af[mf][2] = __float_as_uint(As[r * GPAD + kk + 4]);
                af[mf][3] = __float_as_uint(As[(r + 8) * GPAD + kk + 4]);
            }
            uint32_t bf[4][2];
#pragma unroll
            for (int nf = 0; nf < 4; nf++) {
                const int n = warpCol + nf * 8 + lq;
                bf[nf][0] = __float_as_uint(Ws[n * GPAD + kk]);
                bf[nf][1] = __float_as_uint(Ws[n * GPAD + kk + 4]);
            }
#pragma unroll
            for (int mf = 0; mf < 4; mf++)
#pragma unroll
                for (int nf = 0; nf < 4; nf++)
                    mma_tf32(acc[mf][nf][0], acc[mf][nf][1], acc[mf][nf][2], acc[mf][nf][3],
                             af[mf][0], af[mf][1], af[mf][2], af[mf][3],
                             bf[nf][0], bf[nf][1]);
        }
        __syncthreads();
    }

#pragma unroll
    for (int nf = 0; nf < 4; nf++) {
        const int col = bn + warpCol + nf * 8 + 2 * lr;
        const float b0 = bias[col];
        const float b1 = bias[col + 1];
#pragma unroll
        for (int mf = 0; mf < 4; mf++) {
            const int row = bm + warpRow + mf * 16 + lq;
            float v0 = acc[mf][nf][0] + b0;
            float v1 = acc[mf][nf][1] + b1;
            float v2 = acc[mf][nf][2] + b0;
            float v3 = acc[mf][nf][3] + b1;
            if (round_out) {
                v0 = round_tf32(v0); v1 = round_tf32(v1);
                v2 = round_tf32(v2); v3 = round_tf32(v3);
            }
            *(float2*)(C + (size_t)row * D_MODEL + col) = make_float2(v0, v1);
            *(float2*)(C + (size_t)(row + 8) * D_MODEL + col) = make_float2(v2, v3);
        }
    }
}

// ---------------------------------------------------------------------------
// Flash attention on mma.sync tf32.
// CTA = (b, h, 64 Q rows). 4 warps x 16 rows, 128 threads, 2 CTAs/SM.
// BKV=64 double-buffered cp.async. APAD=72 -> ALL fragment LDS conflict-free
// (Q/K: banks 8*lq+lr; V: banks 8*lr+lq; both full-rank).
// P permuted D-frag -> A-frag via quad shuffles (exact, stays in registers).
// ---------------------------------------------------------------------------
#define AQ_ROWS 64
#define AKV     64
#define APAD    72
#define A_QS_F   (AQ_ROWS * APAD)               // 4608 floats
#define A_KST_F  (AKV * APAD)                   // 4608 floats
#define ATT_SMEM ((A_QS_F + 4 * A_KST_F) * 4)   // 92160 bytes
#define NKT (SEQ / AKV)                         // 32 kv tiles

__global__ void __launch_bounds__(128, 2)
attn_mma(const float* __restrict__ Q,
         const float* __restrict__ Kg,
         const float* __restrict__ Vg,
         float* __restrict__ O) {
    extern __shared__ float smf[];
    float* Qs = smf;                        // [64][72]
    float* Ks[2] = { smf + A_QS_F, smf + A_QS_F + A_KST_F };
    float* Vs[2] = { smf + A_QS_F + 2 * A_KST_F, smf + A_QS_F + 3 * A_KST_F };
    const uint32_t sb = smem_u32(smf);

    const int tid = threadIdx.x;
    const int wid = tid >> 5;     // 0..3
    const int lane = tid & 31;
    const int lq = lane >> 2;
    const int lr = lane & 3;
    const int wrow = wid * 16;

    const int qt = blockIdx.x;
    const int h  = blockIdx.y;
    const int b  = blockIdx.z;

    const float* Qbase = Q + ((size_t)b * SEQ + (size_t)qt * AQ_ROWS) * D_MODEL + h * HEAD_DIM;
    const float* Kbase = Kg + (size_t)b * SEQ * D_MODEL + h * HEAD_DIM;
    const float* Vbase = Vg + (size_t)b * SEQ * D_MODEL + h * HEAD_DIM;

    auto load_kv = [&](int kt) {
        const int st = kt & 1;
        const uint32_t kdst = sb + (uint32_t)(A_QS_F + st * A_KST_F) * 4;
        const uint32_t vdst = sb + (uint32_t)(A_QS_F + (2 + st) * A_KST_F) * 4;
        const float* Kt = Kbase + (size_t)kt * AKV * D_MODEL;
        const float* Vt = Vbase + (size_t)kt * AKV * D_MODEL;
#pragma unroll
        for (int i = 0; i < 8; i++) {
            const int id = tid + i * 128;      // 0..1023
            const int row = id >> 4;
            const int ch = id & 15;
            cpasync16(kdst + row * (APAD * 4) + ch * 16, Kt + (size_t)row * D_MODEL + ch * 4);
            cpasync16(vdst + row * (APAD * 4) + ch * 16, Vt + (size_t)row * D_MODEL + ch * 4);
        }
        cp_commit();
    };

    load_kv(0);

    // Q tile -> smem, scaled by 1/8. 64 rows x 16 chunks = 1024 float4 tasks.
#pragma unroll
    for (int i = 0; i < 8; i++) {
        const int t = tid + i * 128;
        const int row = t >> 4;
        const int c4 = (t & 15) * 4;
        float4 v = *(const float4*)(Qbase + (size_t)row * D_MODEL + c4);
        v.x *= 0.125f; v.y *= 0.125f; v.z *= 0.125f; v.w *= 0.125f;
        *(float4*)&Qs[row * APAD + c4] = v;
    }
    __syncthreads();

    // Q A-fragments: 8 k-chunks x 4 regs
    uint32_t qa[8][4];
#pragma unroll
    for (int kc = 0; kc < 8; kc++) {
        const int r = wrow + lq;
        const int d = kc * 8 + lr;
        qa[kc][0] = __float_as_uint(Qs[r * APAD + d]);
        qa[kc][1] = __float_as_uint(Qs[(r + 8) * APAD + d]);
        qa[kc][2] = __float_as_uint(Qs[r * APAD + d + 4]);
        qa[kc][3] = __float_as_uint(Qs[(r + 8) * APAD + d + 4]);
    }

    float m0 = -1e30f, m1 = -1e30f, l0 = 0.0f, l1 = 0.0f;
    float o[8][4];
#pragma unroll
    for (int nf = 0; nf < 8; nf++)
#pragma unroll
        for (int r = 0; r < 4; r++) o[nf][r] = 0.0f;

    for (int kt = 0; kt < NKT; kt++) {
        cp_wait_group<0>();
        __syncthreads();
        if (kt + 1 < NKT) load_kv(kt + 1);

        const int st = kt & 1;
        const float* Kst = Ks[st];
        const float* Vst = Vs[st];

        // S = Q K^T
        float s[8][4];
#pragma unroll
        for (int nf = 0; nf < 8; nf++) {
            s[nf][0] = s[nf][1] = s[nf][2] = s[nf][3] = 0.0f;
            const int key = nf * 8 + lq;
#pragma unroll
            for (int kc = 0; kc < 8; kc++) {
                const int d = kc * 8 + lr;
                uint32_t b0 = __float_as_uint(Kst[key * APAD + d]);
                uint32_t b1 = __float_as_uint(Kst[key * APAD + d + 4]);
                mma_tf32(s[nf][0], s[nf][1], s[nf][2], s[nf][3],
                         qa[kc][0], qa[kc][1], qa[kc][2], qa[kc][3], b0, b1);
            }
        }

        // online softmax: regs 0,1 -> row wrow+lq; regs 2,3 -> row wrow+lq+8
        float mx0 = -1e30f, mx1 = -1e30f;
#pragma unroll
        for (int nf = 0; nf < 8; nf++) {
            mx0 = fmaxf(mx0, fmaxf(s[nf][0], s[nf][1]));
            mx1 = fmaxf(mx1, fmaxf(s[nf][2], s[nf][3]));
        }
        mx0 = fmaxf(mx0, __shfl_xor_sync(0xffffffffu, mx0, 1));
        mx0 = fmaxf(mx0, __shfl_xor_sync(0xffffffffu, mx0, 2));
        mx1 = fmaxf(mx1, __shfl_xor_sync(0xffffffffu, mx1, 1));
        mx1 = fmaxf(mx1, __shfl_xor_sync(0xffffffffu, mx1, 2));

        const float mn0 = fmaxf(m0, mx0);
        const float mn1 = fmaxf(m1, mx1);
        const float c0 = __expf(m0 - mn0);
        const float c1 = __expf(m1 - mn1);
        m0 = mn0; m1 = mn1;

        float rs0 = 0.0f, rs1 = 0.0f;
#pragma unroll
        for (int nf = 0; nf < 8; nf++) {
            s[nf][0] = round_tf32(__expf(s[nf][0] - mn0));
            s[nf][1] = round_tf32(__expf(s[nf][1] - mn0));
            s[nf][2] = round_tf32(__expf(s[nf][2] - mn1));
            s[nf][3] = round_tf32(__expf(s[nf][3] - mn1));
            rs0 += s[nf][0] + s[nf][1];
            rs1 += s[nf][2] + s[nf][3];
        }
        rs0 += __shfl_xor_sync(0xffffffffu, rs0, 1);
        rs0 += __shfl_xor_sync(0xffffffffu, rs0, 2);
        rs1 += __shfl_xor_sync(0xffffffffu, rs1, 1);
        rs1 += __shfl_xor_sync(0xffffffffu, rs1, 2);
        l0 = l0 * c0 + rs0;
        l1 = l1 * c1 + rs1;

#pragma unroll
        for (int nf = 0; nf < 8; nf++) {
            o[nf][0] *= c0; o[nf][1] *= c0;
            o[nf][2] *= c1; o[nf][3] *= c1;
        }

        // permute P: D-frag cols {2t,2t+1} -> A-frag cols {t, t+4}
        uint32_t pa[8][4];
        const int qb = lane & ~3;
        const int sA = qb | (lr >> 1);
        const int sB = qb | ((lr >> 1) + 2);
        const bool odd = (lr & 1);
#pragma unroll
        for (int kc = 0; kc < 8; kc++) {
            float x0 = __shfl_sync(0xffffffffu, s[kc][0], sA);
            float x1 = __shfl_sync(0xffffffffu, s[kc][1], sA);
            float y0 = __shfl_sync(0xffffffffu, s[kc][0], sB);
            float y1 = __shfl_sync(0xffffffffu, s[kc][1], sB);
            pa[kc][0] = __float_as_uint(odd ? x1 : x0);
            pa[kc][2] = __float_as_uint(odd ? y1 : y0);
            float z0 = __shfl_sync(0xffffffffu, s[kc][2], sA);
            float z1 = __shfl_sync(0xffffffffu, s[kc][3], sA);
            float w0 = __shfl_sync(0xffffffffu, s[kc][2], sB);
            float w1 = __shfl_sync(0xffffffffu, s[kc][3], sB);
            pa[kc][1] = __float_as_uint(odd ? z1 : z0);
            pa[kc][3] = __float_as_uint(odd ? w1 : w0);
        }

        // O += P V   (V fragment LDS conflict-free with APAD=72)
#pragma unroll
        for (int nf2 = 0; nf2 < 8; nf2++) {
            const int dh = nf2 * 8 + lq;
#pragma unroll
            for (int kc = 0; kc < 8; kc++) {
                const int key = kc * 8 + lr;
                uint32_t b0 = __float_as_uint(Vst[key * APAD + dh]);
                uint32_t b1 = __float_as_uint(Vst[(key + 4) * APAD + dh]);
                mma_tf32(o[nf2][0], o[nf2][1], o[nf2][2], o[nf2][3],
                         pa[kc][0], pa[kc][1], pa[kc][2], pa[kc][3], b0, b1);
            }
        }
        __syncthreads();
    }

    // epilogue: normalize, round (feeds Wo mma GEMM), store
    const float inv0 = 1.0f / l0;
    const float inv1 = 1.0f / l1;
    const size_t row0 = (size_t)b * SEQ + (size_t)qt * AQ_ROWS + wrow + lq;
#pragma unroll
    for (int nf2 = 0; nf2 < 8; nf2++) {
        const int col = h * HEAD_DIM + nf2 * 8 + 2 * lr;
        *(float2*)(O + row0 * D_MODEL + col) =
            make_float2(round_tf32(o[nf2][0] * inv0), round_tf32(o[nf2][1] * inv0));
        *(float2*)(O + (row0 + 8) * D_MODEL + col) =
            make_float2(round_tf32(o[nf2][2] * inv1), round_tf32(o[nf2][3] * inv1));
    }
}

// ---------------------------------------------------------------------------
// launch
// ---------------------------------------------------------------------------
extern "C" void kernel_launch(void* const* d_in, const int* in_sizes, int n_in,
                              void* d_out, int out_size) {
    (void)in_sizes; (void)n_in; (void)out_size;

    const float* q  = (const float*)d_in[0];
    const float* k  = (const float*)d_in[1];
    const float* v  = (const float*)d_in[2];
    const float* Wq = (const float*)d_in[3];
    const float* bq = (const float*)d_in[4];
    const float* Wk = (const float*)d_in[5];
    const float* bk = (const float*)d_in[6];
    const float* Wv = (const float*)d_in[7];
    const float* bv = (const float*)d_in[8];
    const float* Wo = (const float*)d_in[9];
    const float* bo = (const float*)d_in[10];
    float* out = (float*)d_out;

    void* sym = nullptr;
    cudaGetSymbolAddress(&sym, g_scratch);
    float* sq = (float*)sym;
    float* sk = sq + (size_t)BT * D_MODEL;
    float* sv = sk + (size_t)BT * D_MODEL;
    float* so = sv + (size_t)BT * D_MODEL;

    void* symr = nullptr;
    cudaGetSymbolAddress(&symr, g_rin);
    float* rq = (float*)symr;
    float* rk = rq + (size_t)BT * D_MODEL;
    float* rv = rk + (size_t)BT * D_MODEL;

    void* symw = nullptr;
    cudaGetSymbolAddress(&symw, g_rw);
    float* rwq = (float*)symw;
    float* rwk = rwq + (size_t)D_MODEL * D_MODEL;
    float* rwv = rwk + (size_t)D_MODEL * D_MODEL;
    float* rwo = rwv + (size_t)D_MODEL * D_MODEL;

    static bool attr_done = false;
    if (!attr_done) {
        cudaFuncSetAttribute(gemm_mma_tf32, cudaFuncAttributeMaxDynamicSharedMemorySize, GEMM_SMEM);
        cudaFuncSetAttribute(attn_mma, cudaFuncAttributeMaxDynamicSharedMemorySize, ATT_SMEM);
        attr_done = true;
    }

    const int n4_in = BT * D_MODEL / 4;
    const int n4_w  = D_MODEL * D_MODEL / 4;

    // launches 1-3: input rounding (kept separate so launch #6 == attn for ncu)
    round_tf32_kernel<<<1024, 256>>>(q, rq, n4_in);
    round_tf32_kernel<<<1024, 256>>>(k, rk, n4_in);
    round_tf32_kernel<<<1024, 256>>>(v, rv, n4_in);

    // launch 4: all four weight roundings in one z-indexed launch
    Ptr4 pw;
    pw.in[0] = Wq; pw.in[1] = Wk; pw.in[2] = Wv; pw.in[3] = Wo;
    pw.out[0] = rwq; pw.out[1] = rwk; pw.out[2] = rwv; pw.out[3] = rwo;
    round_tf32_multi<<<dim3(256, 4), 256>>>(pw, n4_w);

    // launch 5: fused q/k/v projection GEMMs (768 CTAs -> dense waves)
    GemmArgs gqkv;
    gqkv.A[0] = rq;  gqkv.A[1] = rk;  gqkv.A[2] = rv;
    gqkv.W[0] = rwq; gqkv.W[1] = rwk; gqkv.W[2] = rwv;
    gqkv.b[0] = bq;  gqkv.b[1] = bk;  gqkv.b[2] = bv;
    gqkv.C[0] = sq;  gqkv.C[1] = sk;  gqkv.C[2] = sv;
    gqkv.round_out = 1;
    gemm_mma_tf32<<<dim3(D_MODEL / 128, BT / 128, 3), 256, GEMM_SMEM>>>(gqkv);

    // launch 6: attention (profiled slot)
    dim3 aGrid(SEQ / AQ_ROWS, NHEAD, BATCH);  // (32, 16, 2)
    attn_mma<<<aGrid, 128, ATT_SMEM>>>(sq, sk, sv, so);

    // launch 7: output projection
    GemmArgs gout;
    gout.A[0] = so;  gout.A[1] = so;  gout.A[2] = so;
    gout.W[0] = rwo; gout.W[1] = rwo; gout.W[2] = rwo;
    gout.b[0] = bo;  gout.b[1] = bo;  gout.b[2] = bo;
    gout.C[0] = out; gout.C[1] = out; gout.C[2] = out;
    gout.round_out = 0;
    gemm_mma_tf32<<<dim3(D_MODEL / 128, BT / 128, 1), 256, GEMM_SMEM>>>(gout);
}

// round 7
// speedup vs baseline: 3.0256x; 1.0495x over previous
#include <cuda_runtime.h>
#include <cstdint>

#define D_MODEL 1024
#define NHEAD   16
#define HEAD_DIM 64
#define BATCH   2
#define SEQ     2048
#define BT      (BATCH * SEQ)   // 4096 rows

// ---------------------------------------------------------------------------
// Scratch (device globals; no runtime allocation allowed)
// ---------------------------------------------------------------------------
__device__ float g_scratch[4][BT * D_MODEL];           // sq, sk, sv, so

// ---------------------------------------------------------------------------
// Helpers
// ---------------------------------------------------------------------------
__device__ __forceinline__ uint32_t smem_u32(const void* p) {
    uint32_t a;
    asm("{ .reg .u64 t; cvta.to.shared.u64 t, %1; cvt.u32.u64 %0, t; }" : "=r"(a) : "l"(p));
    return a;
}
__device__ __forceinline__ float round_tf32(float x) {
    uint32_t r;
    asm("cvt.rna.tf32.f32 %0, %1;" : "=r"(r) : "f"(x));
    return __uint_as_float(r);
}
__device__ __forceinline__ uint32_t round_tf32_u(float x) {
    uint32_t r;
    asm("cvt.rna.tf32.f32 %0, %1;" : "=r"(r) : "f"(x));
    return r;
}
__device__ __forceinline__ void cpasync16(uint32_t dst, const void* src) {
    asm volatile("cp.async.cg.shared.global [%0], [%1], 16;" :: "r"(dst), "l"(src) : "memory");
}
__device__ __forceinline__ void cp_commit() {
    asm volatile("cp.async.commit_group;" ::: "memory");
}
template <int N>
__device__ __forceinline__ void cp_wait_group() {
    asm volatile("cp.async.wait_group %0;" :: "n"(N) : "memory");
}

// mma.sync m16n8k8 tf32. Fragment layout (CUTLASS SM80_16x8x8_F32TF32TF32F32_TN):
//   A: a0=(g,lr) a1=(g+8,lr) a2=(g,lr+4) a3=(g+8,lr+4)      [g=lane>>2, lr=lane&3]
//   B: b0=B[lr][g] b1=B[lr+4][g]          (B is KxN)
//   C: c0=(g,2lr) c1=(g,2lr+1) c2=(g+8,2lr) c3=(g+8,2lr+1)
__device__ __forceinline__ void mma_tf32(float& d0, float& d1, float& d2, float& d3,
                                         uint32_t a0, uint32_t a1, uint32_t a2, uint32_t a3,
                                         uint32_t b0, uint32_t b1) {
    asm volatile(
        "mma.sync.aligned.m16n8k8.row.col.f32.tf32.tf32.f32 "
        "{%0,%1,%2,%3}, {%4,%5,%6,%7}, {%8,%9}, {%0,%1,%2,%3};"
        : "+f"(d0), "+f"(d1), "+f"(d2), "+f"(d3)
        : "r"(a0), "r"(a1), "r"(a2), "r"(a3), "r"(b0), "r"(b1));
}

// ---------------------------------------------------------------------------
// GEMM: C[M,1024] = A[M,1024] @ W[1024,1024]^T + bias  via mma.sync tf32.
// CTA 128x128, 8 warps in 2x4 (warp tile 64x32), K-step 16, 4-stage cp.async.
// GPAD=20 -> fragment LDS banks (20*lq+lr) mod 32 all distinct.
// Raw fp32 inputs; rna-tf32 rounding fused into the fragment loads.
// blockIdx.z selects the (A, W, bias, C) tuple -> q/k/v fused in one launch.
// ---------------------------------------------------------------------------
#define GSTG 4
#define GPAD 20
#define G_STAGE_FLOATS (2 * 128 * GPAD)        // 5120 floats per stage
#define GEMM_SMEM (GSTG * G_STAGE_FLOATS * 4)  // 81920 bytes
#define G_NS (D_MODEL / 16)                    // 64 K-steps

struct GemmArgs {
    const float* A[3];
    const float* W[3];
    const float* b[3];
    float* C[3];
    int round_out;
};

__global__ void __launch_bounds__(256, 2)
gemm_mma_tf32(GemmArgs ga) {
    extern __shared__ float smf[];
    const uint32_t sb = smem_u32(smf);
    const int tid = threadIdx.x;
    const int wid = tid >> 5;
    const int lane = tid & 31;
    const int lq = lane >> 2;
    const int lr = lane & 3;

    const float* __restrict__ A = ga.A[blockIdx.z];
    const float* __restrict__ W = ga.W[blockIdx.z];
    const float* __restrict__ bias = ga.b[blockIdx.z];
    float* __restrict__ C = ga.C[blockIdx.z];
    const int round_out = ga.round_out;

    const int bm = blockIdx.y * 128;
    const int bn = blockIdx.x * 128;
    const int warpRow = (wid & 1) * 64;
    const int warpCol = (wid >> 1) * 32;

    const int l_row0 = tid >> 2;
    const int l_ch0  = tid & 3;
    const int l_row1 = l_row0 + 64;

    auto load_stage = [&](int s) {
        const int k0 = s * 16;
        const uint32_t smA = sb + (uint32_t)(s & (GSTG - 1)) * (G_STAGE_FLOATS * 4);
        const uint32_t smB = smA + 128 * GPAD * 4;
        cpasync16(smA + l_row0 * (GPAD * 4) + l_ch0 * 16,
                  A + (size_t)(bm + l_row0) * D_MODEL + k0 + l_ch0 * 4);
        cpasync16(smA + l_row1 * (GPAD * 4) + l_ch0 * 16,
                  A + (size_t)(bm + l_row1) * D_MODEL + k0 + l_ch0 * 4);
        cpasync16(smB + l_row0 * (GPAD * 4) + l_ch0 * 16,
                  W + (size_t)(bn + l_row0) * D_MODEL + k0 + l_ch0 * 4);
        cpasync16(smB + l_row1 * (GPAD * 4) + l_ch0 * 16,
                  W + (size_t)(bn + l_row1) * D_MODEL + k0 + l_ch0 * 4);
        cp_commit();
    };

    float acc[4][4][4];
#pragma unroll
    for (int i = 0; i < 4; i++)
#pragma unroll
        for (int j = 0; j < 4; j++)
#pragma unroll
            for (int r = 0; r < 4; r++) acc[i][j][r] = 0.0f;

    load_stage(0);
    load_stage(1);
    load_stage(2);

    for (int s = 0; s < G_NS; s++) {
        cp_wait_group<2>();
        __syncthreads();
        if (s + 3 < G_NS) load_stage(s + 3); else cp_commit();

        const float* As = smf + (size_t)(s & (GSTG - 1)) * G_STAGE_FLOATS;
        const float* Ws = As + 128 * GPAD;

#pragma unroll
        for (int kc = 0; kc < 2; kc++) {
            const int kk = kc * 8 + lr;
            uint32_t af[4][4];
#pragma unroll
            for (int mf = 0; mf < 4; mf++) {
                const int r = warpRow + mf * 16 + lq;
                af[mf][0] = round_tf32_u(As[r * GPAD + kk]);
                af[mf][1] = round_tf32_u(As[(r + 8) * GPAD + kk]);
                af[mf][2] = round_tf32_u(As[r * GPAD + kk + 4]);
                af[mf][3] = round_tf32_u(As[(r + 8) * GPAD + kk + 4]);
            }
            uint32_t bf[4][2];
#pragma unroll
            for (int nf = 0; nf < 4; nf++) {
                const int n = warpCol + nf * 8 + lq;
                bf[nf][0] = round_tf32_u(Ws[n * GPAD + kk]);
                bf[nf][1] = round_tf32_u(Ws[n * GPAD + kk + 4]);
            }
#pragma unroll
            for (int mf = 0; mf < 4; mf++)
#pragma unroll
                for (int nf = 0; nf < 4; nf++)
                    mma_tf32(acc[mf][nf][0], acc[mf][nf][1], acc[mf][nf][2], acc[mf][nf][3],
                             af[mf][0], af[mf][1], af[mf][2], af[mf][3],
                             bf[nf][0], bf[nf][1]);
        }
        __syncthreads();
    }

#pragma unroll
    for (int nf = 0; nf < 4; nf++) {
        const int col = bn + warpCol + nf * 8 + 2 * lr;
        const float b0 = bias[col];
        const float b1 = bias[col + 1];
#pragma unroll
        for (int mf = 0; mf < 4; mf++) {
            const int row = bm + warpRow + mf * 16 + lq;
            float v0 = acc[mf][nf][0] + b0;
            float v1 = acc[mf][nf][1] + b1;
            float v2 = acc[mf][nf][2] + b0;
            float v3 = acc[mf][nf][3] + b1;
            if (round_out) {
                v0 = round_tf32(v0); v1 = round_tf32(v1);
                v2 = round_tf32(v2); v3 = round_tf32(v3);
            }
            *(float2*)(C + (size_t)row * D_MODEL + col) = make_float2(v0, v1);
            *(float2*)(C + (size_t)(row + 8) * D_MODEL + col) = make_float2(v2, v3);
        }
    }
}

// ---------------------------------------------------------------------------
// Flash attention on mma.sync tf32.
// CTA = (b, h, 64 Q rows). 4 warps x 16 rows, 128 threads, 2 CTAs/SM.
// BKV=64 double-buffered cp.async. APAD=72 -> ALL fragment LDS conflict-free.
//
// P handling: NO shuffles. V is stored with its key rows permuted per 8-block
// (even keys -> rows 0..3, odd keys -> rows 4..7), so hardware-k index lr maps
// to key 2lr and lr+4 maps to key 2lr+1. Then the S D-fragment {c0,c1,c2,c3}
// is a valid A-fragment as {a0=c0, a1=c2, a2=c1, a3=c3}.
// ---------------------------------------------------------------------------
#define AQ_ROWS 64
#define AKV     64
#define APAD    72
#define A_QS_F   (AQ_ROWS * APAD)               // 4608 floats
#define A_KST_F  (AKV * APAD)                   // 4608 floats
#define ATT_SMEM ((A_QS_F + 4 * A_KST_F) * 4)   // 92160 bytes
#define NKT (SEQ / AKV)                         // 32 kv tiles

__global__ void __launch_bounds__(128, 2)
attn_mma(const float* __restrict__ Q,
         const float* __restrict__ Kg,
         const float* __restrict__ Vg,
         float* __restrict__ O) {
    extern __shared__ float smf[];
    float* Qs = smf;                        // [64][72]
    float* Ks[2] = { smf + A_QS_F, smf + A_QS_F + A_KST_F };
    float* Vs[2] = { smf + A_QS_F + 2 * A_KST_F, smf + A_QS_F + 3 * A_KST_F };
    const uint32_t sb = smem_u32(smf);

    const int tid = threadIdx.x;
    const int wid = tid >> 5;     // 0..3
    const int lane = tid & 31;
    const int lq = lane >> 2;
    const int lr = lane & 3;
    const int wrow = wid * 16;

    const int qt = blockIdx.x;
    const int h  = blockIdx.y;
    const int b  = blockIdx.z;

    const float* Qbase = Q + ((size_t)b * SEQ + (size_t)qt * AQ_ROWS) * D_MODEL + h * HEAD_DIM;
    const float* Kbase = Kg + (size_t)b * SEQ * D_MODEL + h * HEAD_DIM;
    const float* Vbase = Vg + (size_t)b * SEQ * D_MODEL + h * HEAD_DIM;

    auto load_kv = [&](int kt) {
        const int st = kt & 1;
        const uint32_t kdst = sb + (uint32_t)(A_QS_F + st * A_KST_F) * 4;
        const uint32_t vdst = sb + (uint32_t)(A_QS_F + (2 + st) * A_KST_F) * 4;
        const float* Kt = Kbase + (size_t)kt * AKV * D_MODEL;
        const float* Vt = Vbase + (size_t)kt * AKV * D_MODEL;
#pragma unroll
        for (int i = 0; i < 8; i++) {
            const int id = tid + i * 128;      // 0..1023
            const int row = id >> 4;           // key row 0..63
            const int ch = id & 15;
            // V row permutation: j=row&7; even j -> j/2, odd j -> 4 + j/2
            const int j = row & 7;
            const int vrow = (row & ~7) | ((j & 1) << 2) | (j >> 1);
            cpasync16(kdst + row * (APAD * 4) + ch * 16, Kt + (size_t)row * D_MODEL + ch * 4);
            cpasync16(vdst + vrow * (APAD * 4) + ch * 16, Vt + (size_t)row * D_MODEL + ch * 4);
        }
        cp_commit();
    };

    load_kv(0);

    // Q tile -> smem, scaled by 1/8. 64 rows x 16 chunks = 1024 float4 tasks.
#pragma unroll
    for (int i = 0; i < 8; i++) {
        const int t = tid + i * 128;
        const int row = t >> 4;
        const int c4 = (t & 15) * 4;
        float4 v = *(const float4*)(Qbase + (size_t)row * D_MODEL + c4);
        v.x *= 0.125f; v.y *= 0.125f; v.z *= 0.125f; v.w *= 0.125f;
        *(float4*)&Qs[row * APAD + c4] = v;
    }
    __syncthreads();

    // Q A-fragments: 8 k-chunks x 4 regs
    uint32_t qa[8][4];
#pragma unroll
    for (int kc = 0; kc < 8; kc++) {
        const int r = wrow + lq;
        const int d = kc * 8 + lr;
        qa[kc][0] = __float_as_uint(Qs[r * APAD + d]);
        qa[kc][1] = __float_as_uint(Qs[(r + 8) * APAD + d]);
        qa[kc][2] = __float_as_uint(Qs[r * APAD + d + 4]);
        qa[kc][3] = __float_as_uint(Qs[(r + 8) * APAD + d + 4]);
    }

    float m0 = -1e30f, m1 = -1e30f, l0 = 0.0f, l1 = 0.0f;
    float o[8][4];
#pragma unroll
    for (int nf = 0; nf < 8; nf++)
#pragma unroll
        for (int r = 0; r < 4; r++) o[nf][r] = 0.0f;

    for (int kt = 0; kt < NKT; kt++) {
        cp_wait_group<0>();
        __syncthreads();
        if (kt + 1 < NKT) load_kv(kt + 1);

        const int st = kt & 1;
        const float* Kst = Ks[st];
        const float* Vst = Vs[st];

        // S = Q K^T
        float s[8][4];
#pragma unroll
        for (int nf = 0; nf < 8; nf++) {
            s[nf][0] = s[nf][1] = s[nf][2] = s[nf][3] = 0.0f;
            const int key = nf * 8 + lq;
#pragma unroll
            for (int kc = 0; kc < 8; kc++) {
                const int d = kc * 8 + lr;
                uint32_t b0 = __float_as_uint(Kst[key * APAD + d]);
                uint32_t b1 = __float_as_uint(Kst[key * APAD + d + 4]);
                mma_tf32(s[nf][0], s[nf][1], s[nf][2], s[nf][3],
                         qa[kc][0], qa[kc][1], qa[kc][2], qa[kc][3], b0, b1);
            }
        }

        // online softmax: regs 0,1 -> row wrow+lq; regs 2,3 -> row wrow+lq+8
        float mx0 = -1e30f, mx1 = -1e30f;
#pragma unroll
        for (int nf = 0; nf < 8; nf++) {
            mx0 = fmaxf(mx0, fmaxf(s[nf][0], s[nf][1]));
            mx1 = fmaxf(mx1, fmaxf(s[nf][2], s[nf][3]));
        }
        mx0 = fmaxf(mx0, __shfl_xor_sync(0xffffffffu, mx0, 1));
        mx0 = fmaxf(mx0, __shfl_xor_sync(0xffffffffu, mx0, 2));
        mx1 = fmaxf(mx1, __shfl_xor_sync(0xffffffffu, mx1, 1));
        mx1 = fmaxf(mx1, __shfl_xor_sync(0xffffffffu, mx1, 2));

        const float mn0 = fmaxf(m0, mx0);
        const float mn1 = fmaxf(m1, mx1);
        const float c0 = __expf(m0 - mn0);
        const float c1 = __expf(m1 - mn1);
        m0 = mn0; m1 = mn1;

        float rs0 = 0.0f, rs1 = 0.0f;
#pragma unroll
        for (int nf = 0; nf < 8; nf++) {
            s[nf][0] = round_tf32(__expf(s[nf][0] - mn0));
            s[nf][1] = round_tf32(__expf(s[nf][1] - mn0));
            s[nf][2] = round_tf32(__expf(s[nf][2] - mn1));
            s[nf][3] = round_tf32(__expf(s[nf][3] - mn1));
            rs0 += s[nf][0] + s[nf][1];
            rs1 += s[nf][2] + s[nf][3];
        }
        rs0 += __shfl_xor_sync(0xffffffffu, rs0, 1);
        rs0 += __shfl_xor_sync(0xffffffffu, rs0, 2);
        rs1 += __shfl_xor_sync(0xffffffffu, rs1, 1);
        rs1 += __shfl_xor_sync(0xffffffffu, rs1, 2);
        l0 = l0 * c0 + rs0;
        l1 = l1 * c1 + rs1;

#pragma unroll
        for (int nf = 0; nf < 8; nf++) {
            o[nf][0] *= c0; o[nf][1] *= c0;
            o[nf][2] *= c1; o[nf][3] *= c1;
        }

        // O += P V. V rows permuted => s regs ARE the A-fragment (a1<->a2 swap).
#pragma unroll
        for (int nf2 = 0; nf2 < 8; nf2++) {
            const int dh = nf2 * 8 + lq;
#pragma unroll
            for (int kc = 0; kc < 8; kc++) {
                const int key = kc * 8 + lr;
                uint32_t b0 = __float_as_uint(Vst[key * APAD + dh]);
                uint32_t b1 = __float_as_uint(Vst[(key + 4) * APAD + dh]);
                mma_tf32(o[nf2][0], o[nf2][1], o[nf2][2], o[nf2][3],
                         __float_as_uint(s[kc][0]), __float_as_uint(s[kc][2]),
                         __float_as_uint(s[kc][1]), __float_as_uint(s[kc][3]),
                         b0, b1);
            }
        }
        __syncthreads();
    }

    // epilogue: normalize, round (feeds Wo mma GEMM), store
    const float inv0 = 1.0f / l0;
    const float inv1 = 1.0f / l1;
    const size_t row0 = (size_t)b * SEQ + (size_t)qt * AQ_ROWS + wrow + lq;
#pragma unroll
    for (int nf2 = 0; nf2 < 8; nf2++) {
        const int col = h * HEAD_DIM + nf2 * 8 + 2 * lr;
        *(float2*)(O + row0 * D_MODEL + col) =
            make_float2(round_tf32(o[nf2][0] * inv0), round_tf32(o[nf2][1] * inv0));
        *(float2*)(O + (row0 + 8) * D_MODEL + col) =
            make_float2(round_tf32(o[nf2][2] * inv1), round_tf32(o[nf2][3] * inv1));
    }
}

// ---------------------------------------------------------------------------
// launch
// ---------------------------------------------------------------------------
extern "C" void kernel_launch(void* const* d_in, const int* in_sizes, int n_in,
                              void* d_out, int out_size) {
    (void)in_sizes; (void)n_in; (void)out_size;

    const float* q  = (const float*)d_in[0];
    const float* k  = (const float*)d_in[1];
    const float* v  = (const float*)d_in[2];
    const float* Wq = (const float*)d_in[3];
    const float* bq = (const float*)d_in[4];
    const float* Wk = (const float*)d_in[5];
    const float* bk = (const float*)d_in[6];
    const float* Wv = (const float*)d_in[7];
    const float* bv = (const float*)d_in[8];
    const float* Wo = (const float*)d_in[9];
    const float* bo = (const float*)d_in[10];
    float* out = (float*)d_out;

    void* sym = nullptr;
    cudaGetSymbolAddress(&sym, g_scratch);
    float* sq = (float*)sym;
    float* sk = sq + (size_t)BT * D_MODEL;
    float* sv = sk + (size_t)BT * D_MODEL;
    float* so = sv + (size_t)BT * D_MODEL;

    static bool attr_done = false;
    if (!attr_done) {
        cudaFuncSetAttribute(gemm_mma_tf32, cudaFuncAttributeMaxDynamicSharedMemorySize, GEMM_SMEM);
        cudaFuncSetAttribute(attn_mma, cudaFuncAttributeMaxDynamicSharedMemorySize, ATT_SMEM);
        attr_done = true;
    }

    // launch 1: fused q/k/v projection GEMMs (raw inputs; tf32 rounding fused)
    GemmArgs gqkv;
    gqkv.A[0] = q;  gqkv.A[1] = k;  gqkv.A[2] = v;
    gqkv.W[0] = Wq; gqkv.W[1] = Wk; gqkv.W[2] = Wv;
    gqkv.b[0] = bq; gqkv.b[1] = bk; gqkv.b[2] = bv;
    gqkv.C[0] = sq; gqkv.C[1] = sk; gqkv.C[2] = sv;
    gqkv.round_out = 1;
    gemm_mma_tf32<<<dim3(D_MODEL / 128, BT / 128, 3), 256, GEMM_SMEM>>>(gqkv);

    // launch 2: attention
    dim3 aGrid(SEQ / AQ_ROWS, NHEAD, BATCH);  // (32, 16, 2)
    attn_mma<<<aGrid, 128, ATT_SMEM>>>(sq, sk, sv, so);

    // launch 3: output projection
    GemmArgs gout;
    gout.A[0] = so;  gout.A[1] = so;  gout.A[2] = so;
    gout.W[0] = Wo;  gout.W[1] = Wo;  gout.W[2] = Wo;
    gout.b[0] = bo;  gout.b[1] = bo;  gout.b[2] = bo;
    gout.C[0] = out; gout.C[1] = out; gout.C[2] = out;
    gout.round_out = 0;
    gemm_mma_tf32<<<dim3(D_MODEL / 128, BT / 128, 1), 256, GEMM_SMEM>>>(gout);
}

// round 8
// speedup vs baseline: 3.2246x; 1.0658x over previous
#include <cuda_runtime.h>
#include <cstdint>

#define D_MODEL 1024
#define NHEAD   16
#define HEAD_DIM 64
#define BATCH   2
#define SEQ     2048
#define BT      (BATCH * SEQ)   // 4096 rows

// ---------------------------------------------------------------------------
// Scratch (device globals; no runtime allocation allowed)
// ---------------------------------------------------------------------------
__device__ float g_scratch[4][BT * D_MODEL];           // sq, sk, sv, so

// ---------------------------------------------------------------------------
// Helpers
// ---------------------------------------------------------------------------
__device__ __forceinline__ uint32_t smem_u32(const void* p) {
    uint32_t a;
    asm("{ .reg .u64 t; cvta.to.shared.u64 t, %1; cvt.u32.u64 %0, t; }" : "=r"(a) : "l"(p));
    return a;
}
__device__ __forceinline__ float round_tf32(float x) {
    uint32_t r;
    asm("cvt.rna.tf32.f32 %0, %1;" : "=r"(r) : "f"(x));
    return __uint_as_float(r);
}
__device__ __forceinline__ uint32_t round_tf32_u(float x) {
    uint32_t r;
    asm("cvt.rna.tf32.f32 %0, %1;" : "=r"(r) : "f"(x));
    return r;
}
__device__ __forceinline__ void cpasync16(uint32_t dst, const void* src) {
    asm volatile("cp.async.cg.shared.global [%0], [%1], 16;" :: "r"(dst), "l"(src) : "memory");
}
__device__ __forceinline__ void cp_commit() {
    asm volatile("cp.async.commit_group;" ::: "memory");
}
template <int N>
__device__ __forceinline__ void cp_wait_group() {
    asm volatile("cp.async.wait_group %0;" :: "n"(N) : "memory");
}

// mma.sync m16n8k8 tf32. Fragment layout (CUTLASS SM80_16x8x8_F32TF32TF32F32_TN):
//   A: a0=(g,lr) a1=(g+8,lr) a2=(g,lr+4) a3=(g+8,lr+4)      [g=lane>>2, lr=lane&3]
//   B: b0=B[lr][g] b1=B[lr+4][g]          (B is KxN)
//   C: c0=(g,2lr) c1=(g,2lr+1) c2=(g+8,2lr) c3=(g+8,2lr+1)
__device__ __forceinline__ void mma_tf32(float& d0, float& d1, float& d2, float& d3,
                                         uint32_t a0, uint32_t a1, uint32_t a2, uint32_t a3,
                                         uint32_t b0, uint32_t b1) {
    asm volatile(
        "mma.sync.aligned.m16n8k8.row.col.f32.tf32.tf32.f32 "
        "{%0,%1,%2,%3}, {%4,%5,%6,%7}, {%8,%9}, {%0,%1,%2,%3};"
        : "+f"(d0), "+f"(d1), "+f"(d2), "+f"(d3)
        : "r"(a0), "r"(a1), "r"(a2), "r"(a3), "r"(b0), "r"(b1));
}

// ---------------------------------------------------------------------------
// GEMM: C[M,1024] = A[M,1024] @ W[1024,1024]^T + bias  via mma.sync tf32.
// CTA 128x128, 8 warps in 2x4 (warp tile 64x32).
// K-step 32 (4 x k8 per fragment phase), 3-stage cp.async, ONE sync per iter.
// GPAD=36 -> fragment LDS banks (4lq+lr) mod 32 all distinct.
// Raw fp32 inputs; rna-tf32 rounding fused into fragment loads.
// ---------------------------------------------------------------------------
#define GSTG 3
#define KSTEP 32
#define GPAD 36
#define G_STAGE_FLOATS (2 * 128 * GPAD)        // 9216 floats per stage
#define GEMM_SMEM (GSTG * G_STAGE_FLOATS * 4)  // 110592 bytes
#define G_NS (D_MODEL / KSTEP)                 // 32 iterations

struct GemmArgs {
    const float* A[3];
    const float* W[3];
    const float* b[3];
    float* C[3];
    int round_out;
};

__global__ void __launch_bounds__(256, 2)
gemm_mma_tf32(GemmArgs ga) {
    extern __shared__ float smf[];
    const uint32_t sb = smem_u32(smf);
    const int tid = threadIdx.x;
    const int wid = tid >> 5;
    const int lane = tid & 31;
    const int lq = lane >> 2;
    const int lr = lane & 3;

    const float* __restrict__ A = ga.A[blockIdx.z];
    const float* __restrict__ W = ga.W[blockIdx.z];
    const float* __restrict__ bias = ga.b[blockIdx.z];
    float* __restrict__ C = ga.C[blockIdx.z];
    const int round_out = ga.round_out;

    const int bm = blockIdx.y * 128;
    const int bn = blockIdx.x * 128;
    const int warpRow = (wid & 1) * 64;
    const int warpCol = (wid >> 1) * 32;

    // loader: 1024 16B-chunks per matrix per stage (128 rows x 8 chunks)
    const int l_ch = tid & 7;                  // chunk within 32-float row

    auto load_stage = [&](int s) {
        const int k0 = s * KSTEP;
        const uint32_t smA = sb + (uint32_t)(s % GSTG) * (G_STAGE_FLOATS * 4);
        const uint32_t smB = smA + 128 * GPAD * 4;
#pragma unroll
        for (int i = 0; i < 4; i++) {
            const int row = (tid + i * 256) >> 3;   // 0..127
            cpasync16(smA + row * (GPAD * 4) + l_ch * 16,
                      A + (size_t)(bm + row) * D_MODEL + k0 + l_ch * 4);
            cpasync16(smB + row * (GPAD * 4) + l_ch * 16,
                      W + (size_t)(bn + row) * D_MODEL + k0 + l_ch * 4);
        }
        cp_commit();
    };

    float acc[4][4][4];
#pragma unroll
    for (int i = 0; i < 4; i++)
#pragma unroll
        for (int j = 0; j < 4; j++)
#pragma unroll
            for (int r = 0; r < 4; r++) acc[i][j][r] = 0.0f;

    load_stage(0);
    load_stage(1);

    for (int s = 0; s < G_NS; s++) {
        cp_wait_group<1>();       // stage s resident (in-order group completion)
        __syncthreads();          // all warps done with buffer (s-1)%3 AND see stage s
        if (s + 2 < G_NS) load_stage(s + 2); else cp_commit();  // dummy keeps recency window

        const float* As = smf + (size_t)(s % GSTG) * G_STAGE_FLOATS;
        const float* Ws = As + 128 * GPAD;

#pragma unroll
        for (int kc = 0; kc < 4; kc++) {
            const int kk = kc * 8 + lr;
            uint32_t af[4][4];
#pragma unroll
            for (int mf = 0; mf < 4; mf++) {
                const int r = warpRow + mf * 16 + lq;
                af[mf][0] = round_tf32_u(As[r * GPAD + kk]);
                af[mf][1] = round_tf32_u(As[(r + 8) * GPAD + kk]);
                af[mf][2] = round_tf32_u(As[r * GPAD + kk + 4]);
                af[mf][3] = round_tf32_u(As[(r + 8) * GPAD + kk + 4]);
            }
            uint32_t bf[4][2];
#pragma unroll
            for (int nf = 0; nf < 4; nf++) {
                const int n = warpCol + nf * 8 + lq;
                bf[nf][0] = round_tf32_u(Ws[n * GPAD + kk]);
                bf[nf][1] = round_tf32_u(Ws[n * GPAD + kk + 4]);
            }
#pragma unroll
            for (int mf = 0; mf < 4; mf++)
#pragma unroll
                for (int nf = 0; nf < 4; nf++)
                    mma_tf32(acc[mf][nf][0], acc[mf][nf][1], acc[mf][nf][2], acc[mf][nf][3],
                             af[mf][0], af[mf][1], af[mf][2], af[mf][3],
                             bf[nf][0], bf[nf][1]);
        }
        // NOTE: no bottom sync — the top sync of iter s+1 provides the ordering.
    }

#pragma unroll
    for (int nf = 0; nf < 4; nf++) {
        const int col = bn + warpCol + nf * 8 + 2 * lr;
        const float b0 = bias[col];
        const float b1 = bias[col + 1];
#pragma unroll
        for (int mf = 0; mf < 4; mf++) {
            const int row = bm + warpRow + mf * 16 + lq;
            float v0 = acc[mf][nf][0] + b0;
            float v1 = acc[mf][nf][1] + b1;
            float v2 = acc[mf][nf][2] + b0;
            float v3 = acc[mf][nf][3] + b1;
            if (round_out) {
                v0 = round_tf32(v0); v1 = round_tf32(v1);
                v2 = round_tf32(v2); v3 = round_tf32(v3);
            }
            *(float2*)(C + (size_t)row * D_MODEL + col) = make_float2(v0, v1);
            *(float2*)(C + (size_t)(row + 8) * D_MODEL + col) = make_float2(v2, v3);
        }
    }
}

// ---------------------------------------------------------------------------
// Flash attention on mma.sync tf32.
// CTA = (b, h, 64 Q rows). 4 warps x 16 rows, 128 threads, 2 CTAs/SM.
// BKV=64 double-buffered cp.async. APAD=72 -> ALL fragment LDS conflict-free.
// V key rows permuted per 8-block so the S D-fragment IS the PV A-fragment
// (register swap a1<->a2, zero shuffles). One sync per tile.
// ---------------------------------------------------------------------------
#define AQ_ROWS 64
#define AKV     64
#define APAD    72
#define A_QS_F   (AQ_ROWS * APAD)               // 4608 floats
#define A_KST_F  (AKV * APAD)                   // 4608 floats
#define ATT_SMEM ((A_QS_F + 4 * A_KST_F) * 4)   // 92160 bytes
#define NKT (SEQ / AKV)                         // 32 kv tiles

__global__ void __launch_bounds__(128, 2)
attn_mma(const float* __restrict__ Q,
         const float* __restrict__ Kg,
         const float* __restrict__ Vg,
         float* __restrict__ O) {
    extern __shared__ float smf[];
    float* Qs = smf;                        // [64][72]
    float* Ks[2] = { smf + A_QS_F, smf + A_QS_F + A_KST_F };
    float* Vs[2] = { smf + A_QS_F + 2 * A_KST_F, smf + A_QS_F + 3 * A_KST_F };
    const uint32_t sb = smem_u32(smf);

    const int tid = threadIdx.x;
    const int wid = tid >> 5;     // 0..3
    const int lane = tid & 31;
    const int lq = lane >> 2;
    const int lr = lane & 3;
    const int wrow = wid * 16;

    const int qt = blockIdx.x;
    const int h  = blockIdx.y;
    const int b  = blockIdx.z;

    const float* Qbase = Q + ((size_t)b * SEQ + (size_t)qt * AQ_ROWS) * D_MODEL + h * HEAD_DIM;
    const float* Kbase = Kg + (size_t)b * SEQ * D_MODEL + h * HEAD_DIM;
    const float* Vbase = Vg + (size_t)b * SEQ * D_MODEL + h * HEAD_DIM;

    auto load_kv = [&](int kt) {
        const int st = kt & 1;
        const uint32_t kdst = sb + (uint32_t)(A_QS_F + st * A_KST_F) * 4;
        const uint32_t vdst = sb + (uint32_t)(A_QS_F + (2 + st) * A_KST_F) * 4;
        const float* Kt = Kbase + (size_t)kt * AKV * D_MODEL;
        const float* Vt = Vbase + (size_t)kt * AKV * D_MODEL;
#pragma unroll
        for (int i = 0; i < 8; i++) {
            const int id = tid + i * 128;      // 0..1023
            const int row = id >> 4;           // key row 0..63
            const int ch = id & 15;
            const int j = row & 7;
            const int vrow = (row & ~7) | ((j & 1) << 2) | (j >> 1);
            cpasync16(kdst + row * (APAD * 4) + ch * 16, Kt + (size_t)row * D_MODEL + ch * 4);
            cpasync16(vdst + vrow * (APAD * 4) + ch * 16, Vt + (size_t)row * D_MODEL + ch * 4);
        }
        cp_commit();
    };

    load_kv(0);

    // Q tile -> smem, scaled by 1/8. 64 rows x 16 chunks = 1024 float4 tasks.
#pragma unroll
    for (int i = 0; i < 8; i++) {
        const int t = tid + i * 128;
        const int row = t >> 4;
        const int c4 = (t & 15) * 4;
        float4 v = *(const float4*)(Qbase + (size_t)row * D_MODEL + c4);
        v.x *= 0.125f; v.y *= 0.125f; v.z *= 0.125f; v.w *= 0.125f;
        *(float4*)&Qs[row * APAD + c4] = v;
    }
    __syncthreads();

    // Q A-fragments: 8 k-chunks x 4 regs
    uint32_t qa[8][4];
#pragma unroll
    for (int kc = 0; kc < 8; kc++) {
        const int r = wrow + lq;
        const int d = kc * 8 + lr;
        qa[kc][0] = __float_as_uint(Qs[r * APAD + d]);
        qa[kc][1] = __float_as_uint(Qs[(r + 8) * APAD + d]);
        qa[kc][2] = __float_as_uint(Qs[r * APAD + d + 4]);
        qa[kc][3] = __float_as_uint(Qs[(r + 8) * APAD + d + 4]);
    }

    float m0 = -1e30f, m1 = -1e30f, l0 = 0.0f, l1 = 0.0f;
    float o[8][4];
#pragma unroll
    for (int nf = 0; nf < 8; nf++)
#pragma unroll
        for (int r = 0; r < 4; r++) o[nf][r] = 0.0f;

    for (int kt = 0; kt < NKT; kt++) {
        cp_wait_group<0>();
        __syncthreads();          // tile kt resident; all warps done with kt-1
        if (kt + 1 < NKT) load_kv(kt + 1);

        const int st = kt & 1;
        const float* Kst = Ks[st];
        const float* Vst = Vs[st];

        // S = Q K^T
        float s[8][4];
#pragma unroll
        for (int nf = 0; nf < 8; nf++) {
            s[nf][0] = s[nf][1] = s[nf][2] = s[nf][3] = 0.0f;
            const int key = nf * 8 + lq;
#pragma unroll
            for (int kc = 0; kc < 8; kc++) {
                const int d = kc * 8 + lr;
                uint32_t b0 = __float_as_uint(Kst[key * APAD + d]);
                uint32_t b1 = __float_as_uint(Kst[key * APAD + d + 4]);
                mma_tf32(s[nf][0], s[nf][1], s[nf][2], s[nf][3],
                         qa[kc][0], qa[kc][1], qa[kc][2], qa[kc][3], b0, b1);
            }
        }

        // online softmax
        float mx0 = -1e30f, mx1 = -1e30f;
#pragma unroll
        for (int nf = 0; nf < 8; nf++) {
            mx0 = fmaxf(mx0, fmaxf(s[nf][0], s[nf][1]));
            mx1 = fmaxf(mx1, fmaxf(s[nf][2], s[nf][3]));
        }
        mx0 = fmaxf(mx0, __shfl_xor_sync(0xffffffffu, mx0, 1));
        mx0 = fmaxf(mx0, __shfl_xor_sync(0xffffffffu, mx0, 2));
        mx1 = fmaxf(mx1, __shfl_xor_sync(0xffffffffu, mx1, 1));
        mx1 = fmaxf(mx1, __shfl_xor_sync(0xffffffffu, mx1, 2));

        const float mn0 = fmaxf(m0, mx0);
        const float mn1 = fmaxf(m1, mx1);
        const float c0 = __expf(m0 - mn0);
        const float c1 = __expf(m1 - mn1);
        m0 = mn0; m1 = mn1;

        float rs0 = 0.0f, rs1 = 0.0f;
#pragma unroll
        for (int nf = 0; nf < 8; nf++) {
            s[nf][0] = round_tf32(__expf(s[nf][0] - mn0));
            s[nf][1] = round_tf32(__expf(s[nf][1] - mn0));
            s[nf][2] = round_tf32(__expf(s[nf][2] - mn1));
            s[nf][3] = round_tf32(__expf(s[nf][3] - mn1));
            rs0 += s[nf][0] + s[nf][1];
            rs1 += s[nf][2] + s[nf][3];
        }
        rs0 += __shfl_xor_sync(0xffffffffu, rs0, 1);
        rs0 += __shfl_xor_sync(0xffffffffu, rs0, 2);
        rs1 += __shfl_xor_sync(0xffffffffu, rs1, 1);
        rs1 += __shfl_xor_sync(0xffffffffu, rs1, 2);
        l0 = l0 * c0 + rs0;
        l1 = l1 * c1 + rs1;

#pragma unroll
        for (int nf = 0; nf < 8; nf++) {
            o[nf][0] *= c0; o[nf][1] *= c0;
            o[nf][2] *= c1; o[nf][3] *= c1;
        }

        // O += P V (V rows permuted => s regs ARE the A-fragment via a1<->a2 swap)
#pragma unroll
        for (int nf2 = 0; nf2 < 8; nf2++) {
            const int dh = nf2 * 8 + lq;
#pragma unroll
            for (int kc = 0; kc < 8; kc++) {
                const int key = kc * 8 + lr;
                uint32_t b0 = __float_as_uint(Vst[key * APAD + dh]);
                uint32_t b1 = __float_as_uint(Vst[(key + 4) * APAD + dh]);
                mma_tf32(o[nf2][0], o[nf2][1], o[nf2][2], o[nf2][3],
                         __float_as_uint(s[kc][0]), __float_as_uint(s[kc][2]),
                         __float_as_uint(s[kc][1]), __float_as_uint(s[kc][3]),
                         b0, b1);
            }
        }
        // NOTE: no bottom sync — next iter's top sync provides the ordering.
    }

    // epilogue: normalize, round (feeds Wo mma GEMM), store
    const float inv0 = 1.0f / l0;
    const float inv1 = 1.0f / l1;
    const size_t row0 = (size_t)b * SEQ + (size_t)qt * AQ_ROWS + wrow + lq;
#pragma unroll
    for (int nf2 = 0; nf2 < 8; nf2++) {
        const int col = h * HEAD_DIM + nf2 * 8 + 2 * lr;
        *(float2*)(O + row0 * D_MODEL + col) =
            make_float2(round_tf32(o[nf2][0] * inv0), round_tf32(o[nf2][1] * inv0));
        *(float2*)(O + (row0 + 8) * D_MODEL + col) =
            make_float2(round_tf32(o[nf2][2] * inv1), round_tf32(o[nf2][3] * inv1));
    }
}

// ---------------------------------------------------------------------------
// launch
// ---------------------------------------------------------------------------
extern "C" void kernel_launch(void* const* d_in, const int* in_sizes, int n_in,
                              void* d_out, int out_size) {
    (void)in_sizes; (void)n_in; (void)out_size;

    const float* q  = (const float*)d_in[0];
    const float* k  = (const float*)d_in[1];
    const float* v  = (const float*)d_in[2];
    const float* Wq = (const float*)d_in[3];
    const float* bq = (const float*)d_in[4];
    const float* Wk = (const float*)d_in[5];
    const float* bk = (const float*)d_in[6];
    const float* Wv = (const float*)d_in[7];
    const float* bv = (const float*)d_in[8];
    const float* Wo = (const float*)d_in[9];
    const float* bo = (const float*)d_in[10];
    float* out = (float*)d_out;

    void* sym = nullptr;
    cudaGetSymbolAddress(&sym, g_scratch);
    float* sq = (float*)sym;
    float* sk = sq + (size_t)BT * D_MODEL;
    float* sv = sk + (size_t)BT * D_MODEL;
    float* so = sv + (size_t)BT * D_MODEL;

    static bool attr_done = false;
    if (!attr_done) {
        cudaFuncSetAttribute(gemm_mma_tf32, cudaFuncAttributeMaxDynamicSharedMemorySize, GEMM_SMEM);
        cudaFuncSetAttribute(attn_mma, cudaFuncAttributeMaxDynamicSharedMemorySize, ATT_SMEM);
        attr_done = true;
    }

    // launch 1: fused q/k/v projection GEMMs
    GemmArgs gqkv;
    gqkv.A[0] = q;  gqkv.A[1] = k;  gqkv.A[2] = v;
    gqkv.W[0] = Wq; gqkv.W[1] = Wk; gqkv.W[2] = Wv;
    gqkv.b[0] = bq; gqkv.b[1] = bk; gqkv.b[2] = bv;
    gqkv.C[0] = sq; gqkv.C[1] = sk; gqkv.C[2] = sv;
    gqkv.round_out = 1;
    gemm_mma_tf32<<<dim3(D_MODEL / 128, BT / 128, 3), 256, GEMM_SMEM>>>(gqkv);

    // launch 2: attention
    dim3 aGrid(SEQ / AQ_ROWS, NHEAD, BATCH);  // (32, 16, 2)
    attn_mma<<<aGrid, 128, ATT_SMEM>>>(sq, sk, sv, so);

    // launch 3: output projection
    GemmArgs gout;
    gout.A[0] = so;  gout.A[1] = so;  gout.A[2] = so;
    gout.W[0] = Wo;  gout.W[1] = Wo;  gout.W[2] = Wo;
    gout.b[0] = bo;  gout.b[1] = bo;  gout.b[2] = bo;
    gout.C[0] = out; gout.C[1] = out; gout.C[2] = out;
    gout.round_out = 0;
    gemm_mma_tf32<<<dim3(D_MODEL / 128, BT / 128, 1), 256, GEMM_SMEM>>>(gout);
}